// round 2
// baseline (speedup 1.0000x reference)
#include <cuda_runtime.h>
#include <cuda_bf16.h>
#include <cstdint>

// Problem constants (from reference)
#define NN 50000
#define DD 256
#define RR 16
#define BB 8
#define NB 9              // B + 1 (root folded in)
#define NCOL (NB * DD)    // 2304
#define LN_EPS 1e-5f

// ---- static scratch (no allocs allowed) ----
__device__ float g_W[DD * NCOL];                       // combined weight [256,2304]
__device__ float g_Y[(size_t)NN * NCOL];               // x @ g_W        460.8 MB
__device__ float g_H[(size_t)NN * RR * DD];            // per-relation   819.2 MB
__device__ float g_agg[(size_t)NN * DD];               // edge sums       51.2 MB
__device__ float g_cnt[NN];                            // indeg + 1
__device__ float g_x1[(size_t)NN * DD];                // layer-1 output

// ---------------------------------------------------------------------------
// Build combined weight: g_W[i*2304 + b*256 + o] = basis[b,i,o];
//                        g_W[i*2304 + 2048 + o]  = root[i,o]
__global__ void k_prepw(const float* __restrict__ basis, const float* __restrict__ root) {
    int t = blockIdx.x * 256 + threadIdx.x;
    if (t >= DD * NCOL) return;
    int i = t / NCOL, c = t % NCOL;
    float v;
    if (c < BB * DD) {
        int b = c >> 8, o = c & 255;
        v = basis[((size_t)b * DD + i) * DD + o];
    } else {
        v = root[(size_t)i * DD + (c - BB * DD)];
    }
    g_W[t] = v;
}

// cnt init + edge-degree count
__global__ void k_cnt_init(int M) {
    int n = blockIdx.x * 256 + threadIdx.x;
    if (n < M) g_cnt[n] = 1.0f;
}
__global__ void k_cnt_edges(const int* __restrict__ ei, int E) {
    int t = blockIdx.x * 256 + threadIdx.x;
    if (t < E) atomicAdd(&g_cnt[ei[E + t]], 1.0f);
}

__global__ void k_zero_agg(int M) {
    int t = blockIdx.x * 256 + threadIdx.x;
    int total = M * (DD / 4);
    if (t < total) ((float4*)g_agg)[t] = make_float4(0.f, 0.f, 0.f, 0.f);
}

// ---------------------------------------------------------------------------
// fp32 SIMT GEMM: g_Y[M,2304] = A[M,256] @ g_W[256,2304]
// 128x128 tiles, BK=16, 256 threads, 8x8 per thread.
// NOTE: writes the device symbol g_Y directly (never passed from host).
__global__ __launch_bounds__(256) void k_gemm(const float* __restrict__ A, int M) {
    const int K = DD, Nn = NCOL;
    __shared__ float As[16][128];
    __shared__ float Bs[16][128];
    int tid = threadIdx.x;
    int tx = tid % 16, ty = tid / 16;
    int rowBase = blockIdx.y * 128, colBase = blockIdx.x * 128;
    int aRow = tid >> 2;            // 0..63
    int aCol = (tid & 3) * 4;       // 0,4,8,12
    int bRow = tid >> 5;            // 0..7
    int bCol = (tid & 31) * 4;      // 0..124
    float acc[8][8];
#pragma unroll
    for (int i = 0; i < 8; i++)
#pragma unroll
        for (int j = 0; j < 8; j++) acc[i][j] = 0.f;

    for (int k0 = 0; k0 < K; k0 += 16) {
#pragma unroll
        for (int i = 0; i < 2; i++) {
            int r = aRow + i * 64;
            int gr = rowBase + r;
            float4 v = make_float4(0.f, 0.f, 0.f, 0.f);
            if (gr < M) v = *(const float4*)&A[(size_t)gr * K + k0 + aCol];
            As[aCol + 0][r] = v.x; As[aCol + 1][r] = v.y;
            As[aCol + 2][r] = v.z; As[aCol + 3][r] = v.w;
        }
#pragma unroll
        for (int i = 0; i < 2; i++) {
            int r = bRow + i * 8;
            float4 v = *(const float4*)&g_W[(size_t)(k0 + r) * Nn + colBase + bCol];
            *(float4*)&Bs[r][bCol] = v;
        }
        __syncthreads();
#pragma unroll
        for (int kk = 0; kk < 16; kk++) {
            float ra[8], rb[8];
#pragma unroll
            for (int i = 0; i < 8; i++) ra[i] = As[kk][ty * 8 + i];
#pragma unroll
            for (int j = 0; j < 8; j++) rb[j] = Bs[kk][tx * 8 + j];
#pragma unroll
            for (int i = 0; i < 8; i++)
#pragma unroll
                for (int j = 0; j < 8; j++) acc[i][j] += ra[i] * rb[j];
        }
        __syncthreads();
    }
#pragma unroll
    for (int i = 0; i < 8; i++) {
        int gr = rowBase + ty * 8 + i;
        if (gr >= M) continue;
#pragma unroll
        for (int j = 0; j < 8; j += 4) {
            float4 v = make_float4(acc[i][j], acc[i][j + 1], acc[i][j + 2], acc[i][j + 3]);
            *(float4*)&g_Y[(size_t)gr * Nn + colBase + tx * 8 + j] = v;
        }
    }
}

// ---------------------------------------------------------------------------
// Expand: H[n,r,o] = sum_b att[r,b] * Y[n, b*256+o]
__global__ void k_expand(const float* __restrict__ att, int M) {
    int n = blockIdx.x;
    if (n >= M) return;
    int o = threadIdx.x;
    __shared__ float a[RR][BB];
    if (threadIdx.x < RR * BB) a[threadIdx.x >> 3][threadIdx.x & 7] = att[threadIdx.x];
    __syncthreads();
    float y[BB];
#pragma unroll
    for (int b = 0; b < BB; b++) y[b] = g_Y[(size_t)n * NCOL + b * DD + o];
#pragma unroll
    for (int r = 0; r < RR; r++) {
        float s = 0.f;
#pragma unroll
        for (int b = 0; b < BB; b++) s += a[r][b] * y[b];
        g_H[((size_t)n * RR + r) * DD + o] = s;
    }
}

// ---------------------------------------------------------------------------
// Edge scatter: agg[dst] += ea * H[src, et]   (one warp per edge)
__global__ void k_scatter(const int* __restrict__ ei, const int* __restrict__ et,
                          const float* __restrict__ ea, int E) {
    int warp = (blockIdx.x * blockDim.x + threadIdx.x) >> 5;
    int lane = threadIdx.x & 31;
    if (warp >= E) return;
    int src = ei[warp];
    int dst = ei[E + warp];
    int r   = et[warp];
    float w = ea[warp];
    const float4* h = (const float4*)&g_H[((size_t)src * RR + r) * DD];
    float4* a = (float4*)&g_agg[(size_t)dst * DD];
#pragma unroll
    for (int i = 0; i < 2; i++) {
        float4 v = h[lane + i * 32];
        v.x *= w; v.y *= w; v.z *= w; v.w *= w;
        asm volatile("red.global.add.v4.f32 [%0], {%1,%2,%3,%4};"
                     :: "l"(a + lane + i * 32), "f"(v.x), "f"(v.y), "f"(v.z), "f"(v.w)
                     : "memory");
    }
}

// ---------------------------------------------------------------------------
// Finalize: val = (agg + H_self)/cnt + Y_root + bias + x; LN; ReLU
__global__ void k_finalize(const float* __restrict__ xin, const float* __restrict__ bias,
                           const float* __restrict__ gln, const float* __restrict__ bln,
                           float* __restrict__ out, int M) {
    int n = blockIdx.x;
    if (n >= M) return;
    int o = threadIdx.x;
    size_t no = (size_t)n * DD + o;
    float val = (g_agg[no] + g_H[((size_t)n * RR + (RR - 1)) * DD + o]) / g_cnt[n]
              + g_Y[(size_t)n * NCOL + BB * DD + o] + bias[o] + xin[no];

    __shared__ float red[8];
    __shared__ float sh_mu, sh_rstd;
    // mean
    float s = val;
#pragma unroll
    for (int k = 16; k > 0; k >>= 1) s += __shfl_down_sync(0xffffffffu, s, k);
    if ((o & 31) == 0) red[o >> 5] = s;
    __syncthreads();
    if (o == 0) {
        float t = 0.f;
#pragma unroll
        for (int i = 0; i < 8; i++) t += red[i];
        sh_mu = t * (1.0f / DD);
    }
    __syncthreads();
    float mu = sh_mu;
    float d = val - mu;
    float s2 = d * d;
#pragma unroll
    for (int k = 16; k > 0; k >>= 1) s2 += __shfl_down_sync(0xffffffffu, s2, k);
    if ((o & 31) == 0) red[o >> 5] = s2;
    __syncthreads();
    if (o == 0) {
        float t = 0.f;
#pragma unroll
        for (int i = 0; i < 8; i++) t += red[i];
        sh_rstd = rsqrtf(t * (1.0f / DD) + LN_EPS);
    }
    __syncthreads();
    float y = d * sh_rstd * gln[o] + bln[o];
    out[no] = fmaxf(y, 0.f);
}

// ---------------------------------------------------------------------------
static void run_layer(const float* x, const float* basis, const float* att,
                      const float* root, const float* bias,
                      const float* lg, const float* lb,
                      const int* ei, const int* et, const float* ea,
                      float* out, int M, int E) {
    k_prepw<<<(DD * NCOL + 255) / 256, 256>>>(basis, root);
    k_zero_agg<<<(M * (DD / 4) + 255) / 256, 256>>>(M);
    {
        dim3 grid(NCOL / 128, (M + 127) / 128);
        k_gemm<<<grid, 256>>>(x, M);
    }
    k_expand<<<M, 256>>>(att, M);
    {
        int warpsPerBlock = 8;
        int blocks = (E + warpsPerBlock - 1) / warpsPerBlock;
        k_scatter<<<blocks, 256>>>(ei, et, ea, E);
    }
    k_finalize<<<M, 256>>>(x, bias, lg, lb, out, M);
}

extern "C" void kernel_launch(void* const* d_in, const int* in_sizes, int n_in,
                              void* d_out, int out_size) {
    const float* x   = (const float*)d_in[0];
    const int*   ei  = (const int*)d_in[1];
    const int*   et  = (const int*)d_in[2];
    const float* ea  = (const float*)d_in[3];
    const float* basis1 = (const float*)d_in[4];
    const float* att1   = (const float*)d_in[5];
    const float* root1  = (const float*)d_in[6];
    const float* bias1  = (const float*)d_in[7];
    const float* ln1g   = (const float*)d_in[8];
    const float* ln1b   = (const float*)d_in[9];
    const float* basis2 = (const float*)d_in[10];
    const float* att2   = (const float*)d_in[11];
    const float* root2  = (const float*)d_in[12];
    const float* bias2  = (const float*)d_in[13];
    const float* ln2g   = (const float*)d_in[14];
    const float* ln2b   = (const float*)d_in[15];
    float* out = (float*)d_out;

    int M = in_sizes[0] / DD;     // 50000
    int E = in_sizes[2];          // 800000

    // Proper DEVICE address of the layer-1 output scratch. cudaGetSymbolAddress
    // is a pure address query: no allocation, no stream work, capture-safe.
    static float* x1_dev = nullptr;
    if (x1_dev == nullptr) {
        void* p = nullptr;
        cudaGetSymbolAddress(&p, g_x1);
        x1_dev = (float*)p;
    }

    // degree count (indeg + 1), shared by both layers
    k_cnt_init<<<(M + 255) / 256, 256>>>(M);
    k_cnt_edges<<<(E + 255) / 256, 256>>>(ei, E);

    // layer 1 -> g_x1
    run_layer(x, basis1, att1, root1, bias1, ln1g, ln1b, ei, et, ea, x1_dev, M, E);
    // layer 2 -> out
    run_layer(x1_dev, basis2, att2, root2, bias2, ln2g, ln2b, ei, et, ea, out, M, E);
}

// round 4
// speedup vs baseline: 1.5180x; 1.5180x over previous
#include <cuda_runtime.h>
#include <cuda_bf16.h>
#include <cstdint>

// Problem constants
#define NN 50000
#define DD 256
#define RR 16
#define BB 8
#define NCOL 2304               // 8 basis blocks + root = 9 * 256
#define KK 768                  // 3 * 256 split-K (bf16 fp32-emulation, 3 products)
#define LN_EPS 1e-5f

// ---- static scratch ----
__device__ __nv_bfloat16 g_Ap[(size_t)NN * KK];    // split activations [N,768]
__device__ __nv_bfloat16 g_Bp[(size_t)NCOL * KK];  // split weights [2304,768]
__device__ float g_Y[(size_t)NN * NCOL];           // x @ W  [N,2304]
__device__ float g_H[(size_t)NN * RR * DD];        // per-relation [N,16,256]
__device__ float g_agg[(size_t)NN * DD];           // edge sums
__device__ float g_cnt[NN];                        // indeg + 1
__device__ float g_x1[(size_t)NN * DD];            // layer-1 output

// ===========================================================================
// Prep: split weights. Bp[c,k] over K'=768: [W_hi | W_hi | W_lo] pairing
// A' = [x_hi | x_lo | x_hi]  => hi*hi + lo*hi + hi*lo  (drops lo*lo ~ 2^-18)
// c<2048: Bp = basis[b=c>>8, k, o=c&255];  c>=2048: root[k, c-2048]
__global__ void k_prepw(const float* __restrict__ basis, const float* __restrict__ root) {
    int c = blockIdx.x;      // 0..2303
    int k = threadIdx.x;     // 0..255
    float w;
    if (c < BB * DD) {
        int b = c >> 8, o = c & 255;
        w = basis[((size_t)b * DD + k) * DD + o];
    } else {
        w = root[(size_t)k * DD + (c - BB * DD)];
    }
    __nv_bfloat16 hi = __float2bfloat16(w);
    __nv_bfloat16 lo = __float2bfloat16(w - __bfloat162float(hi));
    size_t base = (size_t)c * KK;
    g_Bp[base + k]       = hi;
    g_Bp[base + 256 + k] = hi;
    g_Bp[base + 512 + k] = lo;
}

// Split activations: A'[n] = [hi(x) | lo(x) | hi(x)]
__global__ void k_split_x(const float* __restrict__ x, int M) {
    int t = blockIdx.x * 256 + threadIdx.x;
    if (t >= M * DD) return;
    int n = t >> 8, k = t & 255;
    float v = x[t];
    __nv_bfloat16 hi = __float2bfloat16(v);
    __nv_bfloat16 lo = __float2bfloat16(v - __bfloat162float(hi));
    size_t base = (size_t)n * KK;
    g_Ap[base + k]       = hi;
    g_Ap[base + 256 + k] = lo;
    g_Ap[base + 512 + k] = hi;
}

__global__ void k_cnt_init(int M) {
    int n = blockIdx.x * 256 + threadIdx.x;
    if (n < M) g_cnt[n] = 1.0f;
}
__global__ void k_cnt_edges(const int* __restrict__ ei, int E) {
    int t = blockIdx.x * 256 + threadIdx.x;
    if (t < E) atomicAdd(&g_cnt[ei[E + t]], 1.0f);
}
__global__ void k_zero_agg(int M) {
    int t = blockIdx.x * 256 + threadIdx.x;
    if (t < M * (DD / 4)) ((float4*)g_agg)[t] = make_float4(0.f, 0.f, 0.f, 0.f);
}

// ===========================================================================
// bf16 mma.sync GEMM: g_Y[M,2304] = A'[M,768] @ B'[2304,768]^T  (fp32 accum)
// 128x128 tile, BK=64, 8 warps (warp tile 64x32), double-buffered smem.
// smem rows padded to 72 bf16 (36 words): bank = (4*row + q) -> conflict-free.
// ===========================================================================
#define BK 64
#define ROWW 36                       // smem row stride in 32-bit words
#define TILE_B 18432                  // 128 * 72 * 2 bytes per tile buffer

static __device__ __forceinline__ void mma16816(float* c, const uint32_t* a,
                                                const uint32_t* b) {
    asm volatile(
        "mma.sync.aligned.m16n8k16.row.col.f32.bf16.bf16.f32 "
        "{%0,%1,%2,%3}, {%4,%5,%6,%7}, {%8,%9}, {%0,%1,%2,%3};\n"
        : "+f"(c[0]), "+f"(c[1]), "+f"(c[2]), "+f"(c[3])
        : "r"(a[0]), "r"(a[1]), "r"(a[2]), "r"(a[3]), "r"(b[0]), "r"(b[1]));
}

__global__ __launch_bounds__(256) void k_gemm_mma(int M) {
    extern __shared__ char smem[];   // [A0 | A1 | B0 | B1], each TILE_B bytes
    const int tid = threadIdx.x;
    const int wid = tid >> 5, lane = tid & 31;
    const int r4 = lane >> 2, q = lane & 3;
    const int rowBase = blockIdx.y * 128;
    const int colBase = blockIdx.x * 128;
    const int wm = (wid >> 2) * 64;      // warp row offset (0 or 64)
    const int wn = (wid & 3) * 32;       // warp col offset (0,32,64,96)

    float acc[4][4][4];
#pragma unroll
    for (int i = 0; i < 4; i++)
#pragma unroll
        for (int j = 0; j < 4; j++)
#pragma unroll
            for (int t = 0; t < 4; t++) acc[i][j][t] = 0.f;

    auto loadTiles = [&](int kt, int buf) {
        int k0 = kt * BK;
        char* sa = smem + buf * TILE_B;
        char* sb = smem + 2 * TILE_B + buf * TILE_B;
#pragma unroll
        for (int i = 0; i < 4; i++) {
            int e = tid + i * 256;           // 1024 chunks of 8 bf16
            int r = e >> 3, c8 = e & 7;
            int gr = rowBase + r;
            uint4 v = make_uint4(0u, 0u, 0u, 0u);
            if (gr < M) v = *(const uint4*)&g_Ap[(size_t)gr * KK + k0 + c8 * 8];
            *(uint4*)(sa + r * 144 + c8 * 16) = v;
        }
#pragma unroll
        for (int i = 0; i < 4; i++) {
            int e = tid + i * 256;
            int r = e >> 3, c8 = e & 7;
            uint4 v = *(const uint4*)&g_Bp[(size_t)(colBase + r) * KK + k0 + c8 * 8];
            *(uint4*)(sb + r * 144 + c8 * 16) = v;
        }
    };

    const int NT = KK / BK;   // 12
    loadTiles(0, 0);
    __syncthreads();

    for (int kt = 0; kt < NT; kt++) {
        int buf = kt & 1;
        if (kt + 1 < NT) loadTiles(kt + 1, buf ^ 1);

        const uint32_t* Aw = (const uint32_t*)(smem + buf * TILE_B);
        const uint32_t* Bw = (const uint32_t*)(smem + 2 * TILE_B + buf * TILE_B);
#pragma unroll
        for (int ks = 0; ks < 4; ks++) {       // 4 x k16 within BK=64
            uint32_t af[4][4], bf[4][2];
#pragma unroll
            for (int mi = 0; mi < 4; mi++) {
                int base = (wm + mi * 16 + r4) * ROWW + ks * 8 + q;
                af[mi][0] = Aw[base];
                af[mi][1] = Aw[base + 8 * ROWW];
                af[mi][2] = Aw[base + 4];
                af[mi][3] = Aw[base + 8 * ROWW + 4];
            }
#pragma unroll
            for (int ni = 0; ni < 4; ni++) {
                int base = (wn + ni * 8 + r4) * ROWW + ks * 8 + q;
                bf[ni][0] = Bw[base];
                bf[ni][1] = Bw[base + 4];
            }
#pragma unroll
            for (int mi = 0; mi < 4; mi++)
#pragma unroll
                for (int ni = 0; ni < 4; ni++)
                    mma16816(acc[mi][ni], af[mi], bf[ni]);
        }
        __syncthreads();
    }

    // Epilogue: C frag (row=lane/4, col=(lane%4)*2), c2/c3 at row+8
#pragma unroll
    for (int mi = 0; mi < 4; mi++) {
        int gr0 = rowBase + wm + mi * 16 + r4;
#pragma unroll
        for (int ni = 0; ni < 4; ni++) {
            int gc = colBase + wn + ni * 8 + q * 2;
            if (gr0 < M)
                *(float2*)&g_Y[(size_t)gr0 * NCOL + gc] =
                    make_float2(acc[mi][ni][0], acc[mi][ni][1]);
            if (gr0 + 8 < M)
                *(float2*)&g_Y[(size_t)(gr0 + 8) * NCOL + gc] =
                    make_float2(acc[mi][ni][2], acc[mi][ni][3]);
        }
    }
}

// ===========================================================================
// Expand: H[n,r,o] = sum_b att[r,b] * Y[n, b*256+o]
__global__ void k_expand(const float* __restrict__ att, int M) {
    int n = blockIdx.x;
    if (n >= M) return;
    int o = threadIdx.x;
    __shared__ float a[RR][BB];
    if (threadIdx.x < RR * BB) a[threadIdx.x >> 3][threadIdx.x & 7] = att[threadIdx.x];
    __syncthreads();
    float y[BB];
#pragma unroll
    for (int b = 0; b < BB; b++) y[b] = g_Y[(size_t)n * NCOL + b * DD + o];
#pragma unroll
    for (int r = 0; r < RR; r++) {
        float s = 0.f;
#pragma unroll
        for (int b = 0; b < BB; b++) s += a[r][b] * y[b];
        g_H[((size_t)n * RR + r) * DD + o] = s;
    }
}

// ===========================================================================
// Edge scatter: agg[dst] += ea * H[src, et]  (one warp per edge)
__global__ void k_scatter(const int* __restrict__ ei, const int* __restrict__ et,
                          const float* __restrict__ ea, int E) {
    int warp = (blockIdx.x * blockDim.x + threadIdx.x) >> 5;
    int lane = threadIdx.x & 31;
    if (warp >= E) return;
    int src = ei[warp];
    int dst = ei[E + warp];
    int r   = et[warp];
    float w = ea[warp];
    const float4* h = (const float4*)&g_H[((size_t)src * RR + r) * DD];
    float4* a = (float4*)&g_agg[(size_t)dst * DD];
#pragma unroll
    for (int i = 0; i < 2; i++) {
        float4 v = h[lane + i * 32];
        v.x *= w; v.y *= w; v.z *= w; v.w *= w;
        asm volatile("red.global.add.v4.f32 [%0], {%1,%2,%3,%4};"
                     :: "l"(a + lane + i * 32), "f"(v.x), "f"(v.y), "f"(v.z), "f"(v.w)
                     : "memory");
    }
}

// ===========================================================================
// Finalize: val = (agg + H_self)/cnt + Y_root + bias + x; LN; ReLU
__global__ void k_finalize(const float* __restrict__ xin, const float* __restrict__ bias,
                           const float* __restrict__ gln, const float* __restrict__ bln,
                           float* __restrict__ out, int M) {
    int n = blockIdx.x;
    if (n >= M) return;
    int o = threadIdx.x;
    size_t no = (size_t)n * DD + o;
    float val = (g_agg[no] + g_H[((size_t)n * RR + (RR - 1)) * DD + o]) / g_cnt[n]
              + g_Y[(size_t)n * NCOL + BB * DD + o] + bias[o] + xin[no];

    __shared__ float red[8];
    __shared__ float sh_mu, sh_rstd;
    float s = val;
#pragma unroll
    for (int k = 16; k > 0; k >>= 1) s += __shfl_down_sync(0xffffffffu, s, k);
    if ((o & 31) == 0) red[o >> 5] = s;
    __syncthreads();
    if (o == 0) {
        float t = 0.f;
#pragma unroll
        for (int i = 0; i < 8; i++) t += red[i];
        sh_mu = t * (1.0f / DD);
    }
    __syncthreads();
    float mu = sh_mu;
    float d = val - mu;
    float s2 = d * d;
#pragma unroll
    for (int k = 16; k > 0; k >>= 1) s2 += __shfl_down_sync(0xffffffffu, s2, k);
    if ((o & 31) == 0) red[o >> 5] = s2;
    __syncthreads();
    if (o == 0) {
        float t = 0.f;
#pragma unroll
        for (int i = 0; i < 8; i++) t += red[i];
        sh_rstd = rsqrtf(t * (1.0f / DD) + LN_EPS);
    }
    __syncthreads();
    float y = d * sh_rstd * gln[o] + bln[o];
    out[no] = fmaxf(y, 0.f);
}

// ===========================================================================
static void run_layer(const float* x, const float* basis, const float* att,
                      const float* root, const float* bias,
                      const float* lg, const float* lb,
                      const int* ei, const int* et, const float* ea,
                      float* out, int M, int E) {
    k_prepw<<<NCOL, 256>>>(basis, root);
    k_split_x<<<(M * DD + 255) / 256, 256>>>(x, M);
    k_zero_agg<<<(M * (DD / 4) + 255) / 256, 256>>>(M);
    {
        dim3 grid(NCOL / 128, (M + 127) / 128);   // (18, 391)
        k_gemm_mma<<<grid, 256, 4 * TILE_B>>>(M);
    }
    k_expand<<<M, 256>>>(att, M);
    k_scatter<<<(E * 32 + 255) / 256, 256>>>(ei, et, ea, E);
    k_finalize<<<M, 256>>>(x, bias, lg, lb, out, M);
}

extern "C" void kernel_launch(void* const* d_in, const int* in_sizes, int n_in,
                              void* d_out, int out_size) {
    const float* x   = (const float*)d_in[0];
    const int*   ei  = (const int*)d_in[1];
    const int*   et  = (const int*)d_in[2];
    const float* ea  = (const float*)d_in[3];
    const float* basis1 = (const float*)d_in[4];
    const float* att1   = (const float*)d_in[5];
    const float* root1  = (const float*)d_in[6];
    const float* bias1  = (const float*)d_in[7];
    const float* ln1g   = (const float*)d_in[8];
    const float* ln1b   = (const float*)d_in[9];
    const float* basis2 = (const float*)d_in[10];
    const float* att2   = (const float*)d_in[11];
    const float* root2  = (const float*)d_in[12];
    const float* bias2  = (const float*)d_in[13];
    const float* ln2g   = (const float*)d_in[14];
    const float* ln2b   = (const float*)d_in[15];
    float* out = (float*)d_out;

    int M = in_sizes[0] / DD;     // 50000
    int E = in_sizes[2];          // 800000

    cudaFuncSetAttribute(k_gemm_mma, cudaFuncAttributeMaxDynamicSharedMemorySize,
                         4 * TILE_B);

    void* p = nullptr;
    cudaGetSymbolAddress(&p, g_x1);
    float* x1_dev = (float*)p;

    k_cnt_init<<<(M + 255) / 256, 256>>>(M);
    k_cnt_edges<<<(E + 255) / 256, 256>>>(ei, E);

    run_layer(x, basis1, att1, root1, bias1, ln1g, ln1b, ei, et, ea, x1_dev, M, E);
    run_layer(x1_dev, basis2, att2, root2, bias2, ln2g, ln2b, ei, et, ea, out, M, E);
}

// round 5
// speedup vs baseline: 1.7114x; 1.1274x over previous
#include <cuda_runtime.h>
#include <cuda_bf16.h>
#include <cstdint>

// Problem constants
#define NN 50000
#define DD 256
#define RR 16
#define BB 8
#define NCOL 2304               // 8 basis blocks + root = 9 * 256
#define KK 768                  // 3 * 256 split-K (bf16 fp32-emulation, 3 products)
#define LN_EPS 1e-5f

// ---- static scratch ----
__device__ __nv_bfloat16 g_Ap[(size_t)NN * KK];    // split activations [N,768]
__device__ __nv_bfloat16 g_Bp[(size_t)NCOL * KK];  // split weights [2304,768]
__device__ float g_Y[(size_t)NN * NCOL];           // x @ W  [N,2304]
__device__ float g_H[(size_t)NN * RR * DD];        // per-relation [N,16,256]
__device__ float g_agg[(size_t)NN * DD];           // edge sums
__device__ float g_cnt[NN];                        // indeg + 1
__device__ float g_x1[(size_t)NN * DD];            // layer-1 output

static __device__ __forceinline__ uint32_t s2u(const void* p) {
    uint32_t a;
    asm("{ .reg .u64 t; cvta.to.shared.u64 t, %1; cvt.u32.u64 %0, t; }" : "=r"(a) : "l"(p));
    return a;
}
#define CP_COMMIT() asm volatile("cp.async.commit_group;" ::: "memory")
#define CP_WAIT(n)  asm volatile("cp.async.wait_group %0;" :: "n"(n) : "memory")

// ===========================================================================
// Prep: split weights. Bp row c over K'=768: [W_hi | W_hi | W_lo]
// pairs with A' = [x_hi | x_lo | x_hi] => hi*hi + lo*hi + hi*lo
__global__ void k_prepw(const float* __restrict__ basis, const float* __restrict__ root) {
    int c = blockIdx.x;      // 0..2303
    int k = threadIdx.x;     // 0..255
    float w;
    if (c < BB * DD) {
        int b = c >> 8, o = c & 255;
        w = basis[((size_t)b * DD + k) * DD + o];
    } else {
        w = root[(size_t)k * DD + (c - BB * DD)];
    }
    __nv_bfloat16 hi = __float2bfloat16(w);
    __nv_bfloat16 lo = __float2bfloat16(w - __bfloat162float(hi));
    size_t base = (size_t)c * KK;
    g_Bp[base + k]       = hi;
    g_Bp[base + 256 + k] = hi;
    g_Bp[base + 512 + k] = lo;
}

// Split activations: A'[n] = [hi(x) | lo(x) | hi(x)]  (layer-1 input only)
__global__ void k_split_x(const float* __restrict__ x, int M) {
    int t = blockIdx.x * 256 + threadIdx.x;
    if (t >= M * DD) return;
    int n = t >> 8, k = t & 255;
    float v = x[t];
    __nv_bfloat16 hi = __float2bfloat16(v);
    __nv_bfloat16 lo = __float2bfloat16(v - __bfloat162float(hi));
    size_t base = (size_t)n * KK;
    g_Ap[base + k]       = hi;
    g_Ap[base + 256 + k] = lo;
    g_Ap[base + 512 + k] = hi;
}

__global__ void k_cnt_init(int M) {
    int n = blockIdx.x * 256 + threadIdx.x;
    if (n < M) g_cnt[n] = 1.0f;
}
__global__ void k_cnt_edges(const int* __restrict__ ei, int E) {
    int t = blockIdx.x * 256 + threadIdx.x;
    if (t < E) atomicAdd(&g_cnt[ei[E + t]], 1.0f);
}
__global__ void k_zero_agg(int M) {
    int t = blockIdx.x * 256 + threadIdx.x;
    if (t < M * (DD / 4)) ((float4*)g_agg)[t] = make_float4(0.f, 0.f, 0.f, 0.f);
}

// ===========================================================================
// bf16 mma.sync GEMM with cp.async double buffering.
// g_Y[M,2304] = A'[M,768] @ B'[2304,768]^T  (fp32 accum)
// 128x128 tile, BK=64, 8 warps (warp tile 64x32).
// smem rows padded to 72 bf16 (144B, 16B-aligned): banks 4*r+q conflict-free.
// ===========================================================================
#define BK 64
#define ROWW 36                       // smem row stride in 32-bit words
#define TILE_B 18432                  // 128 * 144 bytes per tile buffer

static __device__ __forceinline__ void mma16816(float* c, const uint32_t* a,
                                                const uint32_t* b) {
    asm volatile(
        "mma.sync.aligned.m16n8k16.row.col.f32.bf16.bf16.f32 "
        "{%0,%1,%2,%3}, {%4,%5,%6,%7}, {%8,%9}, {%0,%1,%2,%3};\n"
        : "+f"(c[0]), "+f"(c[1]), "+f"(c[2]), "+f"(c[3])
        : "r"(a[0]), "r"(a[1]), "r"(a[2]), "r"(a[3]), "r"(b[0]), "r"(b[1]));
}

__global__ __launch_bounds__(256) void k_gemm_mma(int M) {
    extern __shared__ char smem[];   // [A0 | A1 | B0 | B1], each TILE_B bytes
    const uint32_t sbase = s2u(smem);
    const int tid = threadIdx.x;
    const int wid = tid >> 5, lane = tid & 31;
    const int r4 = lane >> 2, q = lane & 3;
    const int rowBase = blockIdx.y * 128;
    const int colBase = blockIdx.x * 128;
    const int wm = (wid >> 2) * 64;      // warp row offset (0 or 64)
    const int wn = (wid & 3) * 32;       // warp col offset (0,32,64,96)

    float acc[4][4][4];
#pragma unroll
    for (int i = 0; i < 4; i++)
#pragma unroll
        for (int j = 0; j < 4; j++)
#pragma unroll
            for (int t = 0; t < 4; t++) acc[i][j][t] = 0.f;

    // 16B cp.async per thread: A 1024 chunks, B 1024 chunks, 256 threads -> 4+4
    const int rA = tid >> 3;             // 0..31 step: +32 rows per iter? no: e layout
    (void)rA;
    auto issueTiles = [&](int kt, int buf) {
        int k0 = kt * BK;
        uint32_t sa = sbase + buf * TILE_B;
        uint32_t sb = sbase + 2 * TILE_B + buf * TILE_B;
#pragma unroll
        for (int i = 0; i < 4; i++) {
            int e = tid + i * 256;
            int r = e >> 3, c8 = e & 7;
            int gr = rowBase + r;
            uint32_t sz = (gr < M) ? 16u : 0u;
            const void* src = &g_Ap[(size_t)(gr < M ? gr : 0) * KK + k0 + c8 * 8];
            asm volatile("cp.async.cg.shared.global [%0], [%1], 16, %2;"
                         :: "r"(sa + r * 144 + c8 * 16), "l"(src), "r"(sz));
        }
#pragma unroll
        for (int i = 0; i < 4; i++) {
            int e = tid + i * 256;
            int r = e >> 3, c8 = e & 7;
            const void* src = &g_Bp[(size_t)(colBase + r) * KK + k0 + c8 * 8];
            asm volatile("cp.async.cg.shared.global [%0], [%1], 16;"
                         :: "r"(sb + r * 144 + c8 * 16), "l"(src));
        }
    };

    const int NT = KK / BK;   // 12
    issueTiles(0, 0);
    CP_COMMIT();

    for (int kt = 0; kt < NT; kt++) {
        int buf = kt & 1;
        if (kt + 1 < NT) {
            issueTiles(kt + 1, buf ^ 1);
            CP_COMMIT();
            CP_WAIT(1);          // tile kt landed
        } else {
            CP_WAIT(0);
        }
        __syncthreads();

        const uint32_t* Aw = (const uint32_t*)(smem + buf * TILE_B);
        const uint32_t* Bw = (const uint32_t*)(smem + 2 * TILE_B + buf * TILE_B);
#pragma unroll
        for (int ks = 0; ks < 4; ks++) {       // 4 x k16 within BK=64
            uint32_t af[4][4], bf[4][2];
#pragma unroll
            for (int mi = 0; mi < 4; mi++) {
                int base = (wm + mi * 16 + r4) * ROWW + ks * 8 + q;
                af[mi][0] = Aw[base];
                af[mi][1] = Aw[base + 8 * ROWW];
                af[mi][2] = Aw[base + 4];
                af[mi][3] = Aw[base + 8 * ROWW + 4];
            }
#pragma unroll
            for (int ni = 0; ni < 4; ni++) {
                int base = (wn + ni * 8 + r4) * ROWW + ks * 8 + q;
                bf[ni][0] = Bw[base];
                bf[ni][1] = Bw[base + 4];
            }
#pragma unroll
            for (int mi = 0; mi < 4; mi++)
#pragma unroll
                for (int ni = 0; ni < 4; ni++)
                    mma16816(acc[mi][ni], af[mi], bf[ni]);
        }
        __syncthreads();   // before next issue overwrites this buffer
    }

    // Epilogue: C frag (row=r4, col=2q), rows +8 for c2/c3
#pragma unroll
    for (int mi = 0; mi < 4; mi++) {
        int gr0 = rowBase + wm + mi * 16 + r4;
#pragma unroll
        for (int ni = 0; ni < 4; ni++) {
            int gc = colBase + wn + ni * 8 + q * 2;
            if (gr0 < M)
                *(float2*)&g_Y[(size_t)gr0 * NCOL + gc] =
                    make_float2(acc[mi][ni][0], acc[mi][ni][1]);
            if (gr0 + 8 < M)
                *(float2*)&g_Y[(size_t)(gr0 + 8) * NCOL + gc] =
                    make_float2(acc[mi][ni][2], acc[mi][ni][3]);
        }
    }
}

// ===========================================================================
// Expand: H[n,r,o] = sum_b att[r,b] * Y[n, b*256+o]
__global__ void k_expand(const float* __restrict__ att, int M) {
    int n = blockIdx.x;
    if (n >= M) return;
    int o = threadIdx.x;
    __shared__ float a[RR][BB];
    if (threadIdx.x < RR * BB) a[threadIdx.x >> 3][threadIdx.x & 7] = att[threadIdx.x];
    __syncthreads();
    float y[BB];
#pragma unroll
    for (int b = 0; b < BB; b++) y[b] = g_Y[(size_t)n * NCOL + b * DD + o];
#pragma unroll
    for (int r = 0; r < RR; r++) {
        float s = 0.f;
#pragma unroll
        for (int b = 0; b < BB; b++) s += a[r][b] * y[b];
        g_H[((size_t)n * RR + r) * DD + o] = s;
    }
}

// ===========================================================================
// Edge scatter: agg[dst] += ea * H[src, et]  (one warp per edge)
__global__ void k_scatter(const int* __restrict__ ei, const int* __restrict__ et,
                          const float* __restrict__ ea, int E) {
    int warp = (blockIdx.x * blockDim.x + threadIdx.x) >> 5;
    int lane = threadIdx.x & 31;
    if (warp >= E) return;
    int src = ei[warp];
    int dst = ei[E + warp];
    int r   = et[warp];
    float w = ea[warp];
    const float4* h = (const float4*)&g_H[((size_t)src * RR + r) * DD];
    float4* a = (float4*)&g_agg[(size_t)dst * DD];
#pragma unroll
    for (int i = 0; i < 2; i++) {
        float4 v = h[lane + i * 32];
        v.x *= w; v.y *= w; v.z *= w; v.w *= w;
        asm volatile("red.global.add.v4.f32 [%0], {%1,%2,%3,%4};"
                     :: "l"(a + lane + i * 32), "f"(v.x), "f"(v.y), "f"(v.z), "f"(v.w)
                     : "memory");
    }
}

// ===========================================================================
// Finalize: val = (agg + H_self)/cnt + Y_root + bias + x; LN; ReLU
// emit_split: also write [hi|lo|hi] bf16 split of output into g_Ap (next layer)
__global__ void k_finalize(const float* __restrict__ xin, const float* __restrict__ bias,
                           const float* __restrict__ gln, const float* __restrict__ bln,
                           float* __restrict__ out, int M, int emit_split) {
    int n = blockIdx.x;
    if (n >= M) return;
    int o = threadIdx.x;
    size_t no = (size_t)n * DD + o;
    float val = (g_agg[no] + g_H[((size_t)n * RR + (RR - 1)) * DD + o]) / g_cnt[n]
              + g_Y[(size_t)n * NCOL + BB * DD + o] + bias[o] + xin[no];

    __shared__ float red[8];
    __shared__ float sh_mu, sh_rstd;
    float s = val;
#pragma unroll
    for (int k = 16; k > 0; k >>= 1) s += __shfl_down_sync(0xffffffffu, s, k);
    if ((o & 31) == 0) red[o >> 5] = s;
    __syncthreads();
    if (o == 0) {
        float t = 0.f;
#pragma unroll
        for (int i = 0; i < 8; i++) t += red[i];
        sh_mu = t * (1.0f / DD);
    }
    __syncthreads();
    float mu = sh_mu;
    float d = val - mu;
    float s2 = d * d;
#pragma unroll
    for (int k = 16; k > 0; k >>= 1) s2 += __shfl_down_sync(0xffffffffu, s2, k);
    if ((o & 31) == 0) red[o >> 5] = s2;
    __syncthreads();
    if (o == 0) {
        float t = 0.f;
#pragma unroll
        for (int i = 0; i < 8; i++) t += red[i];
        sh_rstd = rsqrtf(t * (1.0f / DD) + LN_EPS);
    }
    __syncthreads();
    float y = fmaxf(d * sh_rstd * gln[o] + bln[o], 0.f);
    out[no] = y;
    if (emit_split) {
        __nv_bfloat16 hi = __float2bfloat16(y);
        __nv_bfloat16 lo = __float2bfloat16(y - __bfloat162float(hi));
        size_t base = (size_t)n * KK;
        g_Ap[base + o]       = hi;
        g_Ap[base + 256 + o] = lo;
        g_Ap[base + 512 + o] = hi;
    }
}

// ===========================================================================
static void run_layer(const float* x, const float* basis, const float* att,
                      const float* root, const float* bias,
                      const float* lg, const float* lb,
                      const int* ei, const int* et, const float* ea,
                      float* out, int M, int E, int emit_split) {
    k_prepw<<<NCOL, 256>>>(basis, root);
    k_zero_agg<<<(M * (DD / 4) + 255) / 256, 256>>>(M);
    {
        dim3 grid(NCOL / 128, (M + 127) / 128);   // (18, 391)
        k_gemm_mma<<<grid, 256, 4 * TILE_B>>>(M);
    }
    k_expand<<<M, 256>>>(att, M);
    k_scatter<<<(E * 32 + 255) / 256, 256>>>(ei, et, ea, E);
    k_finalize<<<M, 256>>>(x, bias, lg, lb, out, M, emit_split);
}

extern "C" void kernel_launch(void* const* d_in, const int* in_sizes, int n_in,
                              void* d_out, int out_size) {
    const float* x   = (const float*)d_in[0];
    const int*   ei  = (const int*)d_in[1];
    const int*   et  = (const int*)d_in[2];
    const float* ea  = (const float*)d_in[3];
    const float* basis1 = (const float*)d_in[4];
    const float* att1   = (const float*)d_in[5];
    const float* root1  = (const float*)d_in[6];
    const float* bias1  = (const float*)d_in[7];
    const float* ln1g   = (const float*)d_in[8];
    const float* ln1b   = (const float*)d_in[9];
    const float* basis2 = (const float*)d_in[10];
    const float* att2   = (const float*)d_in[11];
    const float* root2  = (const float*)d_in[12];
    const float* bias2  = (const float*)d_in[13];
    const float* ln2g   = (const float*)d_in[14];
    const float* ln2b   = (const float*)d_in[15];
    float* out = (float*)d_out;

    int M = in_sizes[0] / DD;     // 50000
    int E = in_sizes[2];          // 800000

    cudaFuncSetAttribute(k_gemm_mma, cudaFuncAttributeMaxDynamicSharedMemorySize,
                         4 * TILE_B);

    void* p = nullptr;
    cudaGetSymbolAddress(&p, g_x1);
    float* x1_dev = (float*)p;

    k_cnt_init<<<(M + 255) / 256, 256>>>(M);
    k_cnt_edges<<<(E + 255) / 256, 256>>>(ei, E);

    // layer 1: split input x, finalize emits split of x1 for layer 2
    k_split_x<<<(M * DD + 255) / 256, 256>>>(x, M);
    run_layer(x, basis1, att1, root1, bias1, ln1g, ln1b, ei, et, ea, x1_dev, M, E, 1);
    // layer 2: g_Ap already populated by layer-1 finalize
    run_layer(x1_dev, basis2, att2, root2, bias2, ln2g, ln2b, ei, et, ea, out, M, E, 0);
}

// round 6
// speedup vs baseline: 1.7475x; 1.0211x over previous
#include <cuda_runtime.h>
#include <cuda_bf16.h>
#include <cstdint>

// Problem constants
#define NN 50000
#define DD 256
#define RR 16
#define BB 8
#define NCOL 2304               // 8 basis blocks + root = 9 * 256
#define KK 768                  // 3 * 256 split-K (bf16 fp32-emulation, 3 products)
#define LN_EPS 1e-5f

// ---- static scratch ----
__device__ __nv_bfloat16 g_Ap[(size_t)NN * KK];    // split activations [N,768]
__device__ __nv_bfloat16 g_Bp[(size_t)NCOL * KK];  // split weights [2304,768]
__device__ float g_Y[(size_t)NN * NCOL];           // x @ W  [N,2304]
__device__ float g_H[(size_t)NN * RR * DD];        // per-relation [N,16,256]
__device__ float g_agg[(size_t)NN * DD];           // edge sums
__device__ float g_cnt[NN];                        // indeg + 1
__device__ float g_x1[(size_t)NN * DD];            // layer-1 output

static __device__ __forceinline__ uint32_t s2u(const void* p) {
    uint32_t a;
    asm("{ .reg .u64 t; cvta.to.shared.u64 t, %1; cvt.u32.u64 %0, t; }" : "=r"(a) : "l"(p));
    return a;
}
#define CP_COMMIT() asm volatile("cp.async.commit_group;" ::: "memory")
#define CP_WAIT(n)  asm volatile("cp.async.wait_group %0;" :: "n"(n) : "memory")
#define LDSM4(r, addr) \
    asm volatile("ldmatrix.sync.aligned.m8n8.x4.shared.b16 {%0,%1,%2,%3}, [%4];" \
        : "=r"((r)[0]), "=r"((r)[1]), "=r"((r)[2]), "=r"((r)[3]) : "r"(addr))

// ===========================================================================
// Prep: split weights. Bp row c over K'=768: [W_hi | W_hi | W_lo]
// pairs with A' = [x_hi | x_lo | x_hi] => hi*hi + lo*hi + hi*lo
__global__ void k_prepw(const float* __restrict__ basis, const float* __restrict__ root) {
    int c = blockIdx.x;      // 0..2303
    int k = threadIdx.x;     // 0..255
    float w;
    if (c < BB * DD) {
        int b = c >> 8, o = c & 255;
        w = basis[((size_t)b * DD + k) * DD + o];
    } else {
        w = root[(size_t)k * DD + (c - BB * DD)];
    }
    __nv_bfloat16 hi = __float2bfloat16(w);
    __nv_bfloat16 lo = __float2bfloat16(w - __bfloat162float(hi));
    size_t base = (size_t)c * KK;
    g_Bp[base + k]       = hi;
    g_Bp[base + 256 + k] = hi;
    g_Bp[base + 512 + k] = lo;
}

// Split activations: A'[n] = [hi(x) | lo(x) | hi(x)]  (layer-1 input only)
__global__ void k_split_x(const float* __restrict__ x, int M) {
    int t = blockIdx.x * 256 + threadIdx.x;
    if (t >= M * DD) return;
    int n = t >> 8, k = t & 255;
    float v = x[t];
    __nv_bfloat16 hi = __float2bfloat16(v);
    __nv_bfloat16 lo = __float2bfloat16(v - __bfloat162float(hi));
    size_t base = (size_t)n * KK;
    g_Ap[base + k]       = hi;
    g_Ap[base + 256 + k] = lo;
    g_Ap[base + 512 + k] = hi;
}

__global__ void k_cnt_init(int M) {
    int n = blockIdx.x * 256 + threadIdx.x;
    if (n < M) g_cnt[n] = 1.0f;
}
__global__ void k_cnt_edges(const int* __restrict__ ei, int E) {
    int t = blockIdx.x * 256 + threadIdx.x;
    if (t < E) atomicAdd(&g_cnt[ei[E + t]], 1.0f);
}
__global__ void k_zero_agg(int M) {
    int t = blockIdx.x * 256 + threadIdx.x;
    if (t < M * (DD / 4)) ((float4*)g_agg)[t] = make_float4(0.f, 0.f, 0.f, 0.f);
}

// ===========================================================================
// bf16 mma.sync GEMM, cp.async double buffering, ldmatrix fragment loads.
// g_Y[M,2304] = A'[M,768] @ B'[2304,768]^T  (fp32 accum)
// 128x128 tile, BK=64, 8 warps (warp tile 64x32).
// smem rows padded to 144B: LDSM rows hit bank groups 4(r+c) mod 32 -> clean.
// ===========================================================================
#define BK 64
#define TILE_B 18432                  // 128 * 144 bytes per tile buffer

static __device__ __forceinline__ void mma16816(float* c, const uint32_t* a,
                                                const uint32_t* b) {
    asm volatile(
        "mma.sync.aligned.m16n8k16.row.col.f32.bf16.bf16.f32 "
        "{%0,%1,%2,%3}, {%4,%5,%6,%7}, {%8,%9}, {%0,%1,%2,%3};\n"
        : "+f"(c[0]), "+f"(c[1]), "+f"(c[2]), "+f"(c[3])
        : "r"(a[0]), "r"(a[1]), "r"(a[2]), "r"(a[3]), "r"(b[0]), "r"(b[1]));
}

__global__ __launch_bounds__(256) void k_gemm_mma(int M) {
    extern __shared__ char smem[];   // [A0 | A1 | B0 | B1], each TILE_B bytes
    const uint32_t sbase = s2u(smem);
    const int tid = threadIdx.x;
    const int wid = tid >> 5, lane = tid & 31;
    const int r4 = lane >> 2, q = lane & 3;
    const int rowBase = blockIdx.y * 128;
    const int colBase = blockIdx.x * 128;
    const int wm = (wid >> 2) * 64;      // warp row offset (0 or 64)
    const int wn = (wid & 3) * 32;       // warp col offset (0,32,64,96)

    float acc[4][4][4];
#pragma unroll
    for (int i = 0; i < 4; i++)
#pragma unroll
        for (int j = 0; j < 4; j++)
#pragma unroll
            for (int t = 0; t < 4; t++) acc[i][j][t] = 0.f;

    // ldmatrix per-lane byte offsets (within a tile buffer)
    // A x4 (mi): mat0 rows0-7/k0-7, mat1 rows8-15/k0-7, mat2 rows0-7/k8-15, mat3 rows8-15/k8-15
    uint32_t aOff[4];
#pragma unroll
    for (int mi = 0; mi < 4; mi++)
        aOff[mi] = (uint32_t)((wm + mi * 16 + (lane & 15)) * 144 + ((lane >> 4) & 1) * 16);
    // B x4 (p): mat0 n0-7/k0-7, mat1 n0-7/k8-15, mat2 n8-15/k0-7, mat3 n8-15/k8-15
    uint32_t bOff[2];
#pragma unroll
    for (int p = 0; p < 2; p++)
        bOff[p] = (uint32_t)((wn + p * 16 + ((lane & 16) >> 1) + (lane & 7)) * 144
                             + ((lane >> 3) & 1) * 16);

    auto issueTiles = [&](int kt, int buf) {
        int k0 = kt * BK;
        uint32_t sa = sbase + buf * TILE_B;
        uint32_t sb = sbase + 2 * TILE_B + buf * TILE_B;
#pragma unroll
        for (int i = 0; i < 4; i++) {
            int e = tid + i * 256;
            int r = e >> 3, c8 = e & 7;
            int gr = rowBase + r;
            uint32_t sz = (gr < M) ? 16u : 0u;
            const void* src = &g_Ap[(size_t)(gr < M ? gr : 0) * KK + k0 + c8 * 8];
            asm volatile("cp.async.cg.shared.global [%0], [%1], 16, %2;"
                         :: "r"(sa + r * 144 + c8 * 16), "l"(src), "r"(sz));
        }
#pragma unroll
        for (int i = 0; i < 4; i++) {
            int e = tid + i * 256;
            int r = e >> 3, c8 = e & 7;
            const void* src = &g_Bp[(size_t)(colBase + r) * KK + k0 + c8 * 8];
            asm volatile("cp.async.cg.shared.global [%0], [%1], 16;"
                         :: "r"(sb + r * 144 + c8 * 16), "l"(src));
        }
    };

    const int NT = KK / BK;   // 12
    issueTiles(0, 0);
    CP_COMMIT();

    for (int kt = 0; kt < NT; kt++) {
        int buf = kt & 1;
        if (kt + 1 < NT) {
            issueTiles(kt + 1, buf ^ 1);
            CP_COMMIT();
            CP_WAIT(1);          // tile kt landed
        } else {
            CP_WAIT(0);
        }
        __syncthreads();

        uint32_t sa = sbase + buf * TILE_B;
        uint32_t sb = sbase + 2 * TILE_B + buf * TILE_B;
#pragma unroll
        for (int ks = 0; ks < 4; ks++) {       // 4 x k16 within BK=64
            uint32_t af[4][4], bf[2][4];
#pragma unroll
            for (int mi = 0; mi < 4; mi++) LDSM4(af[mi], sa + aOff[mi] + ks * 32);
#pragma unroll
            for (int p = 0; p < 2; p++)    LDSM4(bf[p], sb + bOff[p] + ks * 32);
#pragma unroll
            for (int mi = 0; mi < 4; mi++)
#pragma unroll
                for (int ni = 0; ni < 4; ni++)
                    mma16816(acc[mi][ni], af[mi], &bf[ni >> 1][(ni & 1) * 2]);
        }
        __syncthreads();   // before next issue overwrites this buffer
    }

    // Epilogue: C frag (row=r4, col=2q), rows +8 for c2/c3
#pragma unroll
    for (int mi = 0; mi < 4; mi++) {
        int gr0 = rowBase + wm + mi * 16 + r4;
#pragma unroll
        for (int ni = 0; ni < 4; ni++) {
            int gc = colBase + wn + ni * 8 + q * 2;
            if (gr0 < M)
                *(float2*)&g_Y[(size_t)gr0 * NCOL + gc] =
                    make_float2(acc[mi][ni][0], acc[mi][ni][1]);
            if (gr0 + 8 < M)
                *(float2*)&g_Y[(size_t)(gr0 + 8) * NCOL + gc] =
                    make_float2(acc[mi][ni][2], acc[mi][ni][3]);
        }
    }
}

// ===========================================================================
// Expand: H[n,r,o] = sum_b att[r,b] * Y[n, b*256+o]
__global__ void k_expand(const float* __restrict__ att, int M) {
    int n = blockIdx.x;
    if (n >= M) return;
    int o = threadIdx.x;
    __shared__ float a[RR][BB];
    if (threadIdx.x < RR * BB) a[threadIdx.x >> 3][threadIdx.x & 7] = att[threadIdx.x];
    __syncthreads();
    float y[BB];
#pragma unroll
    for (int b = 0; b < BB; b++) y[b] = g_Y[(size_t)n * NCOL + b * DD + o];
#pragma unroll
    for (int r = 0; r < RR; r++) {
        float s = 0.f;
#pragma unroll
        for (int b = 0; b < BB; b++) s += a[r][b] * y[b];
        g_H[((size_t)n * RR + r) * DD + o] = s;
    }
}

// ===========================================================================
// Edge scatter: agg[dst] += ea * H[src, et]  (one warp per edge)
__global__ void k_scatter(const int* __restrict__ ei, const int* __restrict__ et,
                          const float* __restrict__ ea, int E) {
    int warp = (blockIdx.x * blockDim.x + threadIdx.x) >> 5;
    int lane = threadIdx.x & 31;
    if (warp >= E) return;
    int src = ei[warp];
    int dst = ei[E + warp];
    int r   = et[warp];
    float w = ea[warp];
    const float4* h = (const float4*)&g_H[((size_t)src * RR + r) * DD];
    float4* a = (float4*)&g_agg[(size_t)dst * DD];
#pragma unroll
    for (int i = 0; i < 2; i++) {
        float4 v = h[lane + i * 32];
        v.x *= w; v.y *= w; v.z *= w; v.w *= w;
        asm volatile("red.global.add.v4.f32 [%0], {%1,%2,%3,%4};"
                     :: "l"(a + lane + i * 32), "f"(v.x), "f"(v.y), "f"(v.z), "f"(v.w)
                     : "memory");
    }
}

// ===========================================================================
// Finalize: val = (agg + H_self)/cnt + Y_root + bias + x; LN; ReLU
// emit_split: also write [hi|lo|hi] bf16 split of output into g_Ap (next layer)
__global__ void k_finalize(const float* __restrict__ xin, const float* __restrict__ bias,
                           const float* __restrict__ gln, const float* __restrict__ bln,
                           float* __restrict__ out, int M, int emit_split) {
    int n = blockIdx.x;
    if (n >= M) return;
    int o = threadIdx.x;
    size_t no = (size_t)n * DD + o;
    float val = (g_agg[no] + g_H[((size_t)n * RR + (RR - 1)) * DD + o]) / g_cnt[n]
              + g_Y[(size_t)n * NCOL + BB * DD + o] + bias[o] + xin[no];

    __shared__ float red[8];
    __shared__ float sh_mu, sh_rstd;
    float s = val;
#pragma unroll
    for (int k = 16; k > 0; k >>= 1) s += __shfl_down_sync(0xffffffffu, s, k);
    if ((o & 31) == 0) red[o >> 5] = s;
    __syncthreads();
    if (o == 0) {
        float t = 0.f;
#pragma unroll
        for (int i = 0; i < 8; i++) t += red[i];
        sh_mu = t * (1.0f / DD);
    }
    __syncthreads();
    float mu = sh_mu;
    float d = val - mu;
    float s2 = d * d;
#pragma unroll
    for (int k = 16; k > 0; k >>= 1) s2 += __shfl_down_sync(0xffffffffu, s2, k);
    if ((o & 31) == 0) red[o >> 5] = s2;
    __syncthreads();
    if (o == 0) {
        float t = 0.f;
#pragma unroll
        for (int i = 0; i < 8; i++) t += red[i];
        sh_rstd = rsqrtf(t * (1.0f / DD) + LN_EPS);
    }
    __syncthreads();
    float y = fmaxf(d * sh_rstd * gln[o] + bln[o], 0.f);
    out[no] = y;
    if (emit_split) {
        __nv_bfloat16 hi = __float2bfloat16(y);
        __nv_bfloat16 lo = __float2bfloat16(y - __bfloat162float(hi));
        size_t base = (size_t)n * KK;
        g_Ap[base + o]       = hi;
        g_Ap[base + 256 + o] = lo;
        g_Ap[base + 512 + o] = hi;
    }
}

// ===========================================================================
static void run_layer(const float* x, const float* basis, const float* att,
                      const float* root, const float* bias,
                      const float* lg, const float* lb,
                      const int* ei, const int* et, const float* ea,
                      float* out, int M, int E, int emit_split) {
    k_prepw<<<NCOL, 256>>>(basis, root);
    k_zero_agg<<<(M * (DD / 4) + 255) / 256, 256>>>(M);
    {
        dim3 grid(NCOL / 128, (M + 127) / 128);   // (18, 391)
        k_gemm_mma<<<grid, 256, 4 * TILE_B>>>(M);
    }
    k_expand<<<M, 256>>>(att, M);
    k_scatter<<<(E * 32 + 255) / 256, 256>>>(ei, et, ea, E);
    k_finalize<<<M, 256>>>(x, bias, lg, lb, out, M, emit_split);
}

extern "C" void kernel_launch(void* const* d_in, const int* in_sizes, int n_in,
                              void* d_out, int out_size) {
    const float* x   = (const float*)d_in[0];
    const int*   ei  = (const int*)d_in[1];
    const int*   et  = (const int*)d_in[2];
    const float* ea  = (const float*)d_in[3];
    const float* basis1 = (const float*)d_in[4];
    const float* att1   = (const float*)d_in[5];
    const float* root1  = (const float*)d_in[6];
    const float* bias1  = (const float*)d_in[7];
    const float* ln1g   = (const float*)d_in[8];
    const float* ln1b   = (const float*)d_in[9];
    const float* basis2 = (const float*)d_in[10];
    const float* att2   = (const float*)d_in[11];
    const float* root2  = (const float*)d_in[12];
    const float* bias2  = (const float*)d_in[13];
    const float* ln2g   = (const float*)d_in[14];
    const float* ln2b   = (const float*)d_in[15];
    float* out = (float*)d_out;

    int M = in_sizes[0] / DD;     // 50000
    int E = in_sizes[2];          // 800000

    cudaFuncSetAttribute(k_gemm_mma, cudaFuncAttributeMaxDynamicSharedMemorySize,
                         4 * TILE_B);

    void* p = nullptr;
    cudaGetSymbolAddress(&p, g_x1);
    float* x1_dev = (float*)p;

    k_cnt_init<<<(M + 255) / 256, 256>>>(M);
    k_cnt_edges<<<(E + 255) / 256, 256>>>(ei, E);

    // layer 1: split input x, finalize emits split of x1 for layer 2
    k_split_x<<<(M * DD + 255) / 256, 256>>>(x, M);
    run_layer(x, basis1, att1, root1, bias1, ln1g, ln1b, ei, et, ea, x1_dev, M, E, 1);
    // layer 2: g_Ap already populated by layer-1 finalize
    run_layer(x1_dev, basis2, att2, root2, bias2, ln2g, ln2b, ei, et, ea, out, M, E, 0);
}

// round 7
// speedup vs baseline: 2.2183x; 1.2694x over previous
#include <cuda_runtime.h>
#include <cuda_fp16.h>
#include <cstdint>

// Problem constants
#define NN 50000
#define DD 256
#define RR 16
#define BB 8
#define NCOL 2304               // 8 basis blocks + root = 9 * 256
#define KK 512                  // 2 * 256 split-K (fp16 2-product emulation)
#define LN_EPS 1e-5f

// ---- static scratch ----
__device__ __half g_Ap[(size_t)NN * KK];     // split activations [N,512]  51.2MB
__device__ __half g_Bp[(size_t)NCOL * KK];   // split weights [2304,512]    2.4MB
__device__ __half g_Y[(size_t)NN * NCOL];    // x @ W  [N,2304] fp16      230.4MB
__device__ __half g_H[(size_t)NN * RR * DD]; // per-relation fp16         409.6MB
__device__ float g_agg[(size_t)NN * DD];     // edge sums (fp32)           51.2MB
__device__ float g_cnt[NN];                  // indeg + 1
__device__ float g_x1[(size_t)NN * DD];      // layer-1 output

static __device__ __forceinline__ uint32_t s2u(const void* p) {
    uint32_t a;
    asm("{ .reg .u64 t; cvta.to.shared.u64 t, %1; cvt.u32.u64 %0, t; }" : "=r"(a) : "l"(p));
    return a;
}
#define CP_COMMIT() asm volatile("cp.async.commit_group;" ::: "memory")
#define CP_WAIT(n)  asm volatile("cp.async.wait_group %0;" :: "n"(n) : "memory")
#define LDSM4(r, addr) \
    asm volatile("ldmatrix.sync.aligned.m8n8.x4.shared.b16 {%0,%1,%2,%3}, [%4];" \
        : "=r"((r)[0]), "=r"((r)[1]), "=r"((r)[2]), "=r"((r)[3]) : "r"(addr))

// ===========================================================================
// Prep: weights. B' row c = [w_hi | w_hi] (fp16). Pairs with A' = [x_hi | x_lo]:
// hi*whi + lo*whi = x*whi; residual = x*w_lo ~ 1.4e-4 RMS.
__global__ void k_prepw(const float* __restrict__ basis, const float* __restrict__ root) {
    int c = blockIdx.x;      // 0..2303
    int k = threadIdx.x;     // 0..255
    float w;
    if (c < BB * DD) {
        int b = c >> 8, o = c & 255;
        w = basis[((size_t)b * DD + k) * DD + o];
    } else {
        w = root[(size_t)k * DD + (c - BB * DD)];
    }
    __half hi = __float2half_rn(w);
    size_t base = (size_t)c * KK;
    g_Bp[base + k]       = hi;
    g_Bp[base + 256 + k] = hi;
}

// Split activations: A'[n] = [hi(x) | lo(x)]  (fp16)
__global__ void k_split_x(const float* __restrict__ x, int M) {
    int t = blockIdx.x * 256 + threadIdx.x;
    if (t >= M * DD) return;
    int n = t >> 8, k = t & 255;
    float v = x[t];
    __half hi = __float2half_rn(v);
    __half lo = __float2half_rn(v - __half2float(hi));
    size_t base = (size_t)n * KK;
    g_Ap[base + k]       = hi;
    g_Ap[base + 256 + k] = lo;
}

__global__ void k_cnt_init(int M) {
    int n = blockIdx.x * 256 + threadIdx.x;
    if (n < M) g_cnt[n] = 1.0f;
}
__global__ void k_cnt_edges(const int* __restrict__ ei, int E) {
    int t = blockIdx.x * 256 + threadIdx.x;
    if (t < E) atomicAdd(&g_cnt[ei[E + t]], 1.0f);
}
__global__ void k_zero_agg(int M) {
    int t = blockIdx.x * 256 + threadIdx.x;
    if (t < M * (DD / 4)) ((float4*)g_agg)[t] = make_float4(0.f, 0.f, 0.f, 0.f);
}

// ===========================================================================
// fp16 mma.sync GEMM, cp.async double buffering, ldmatrix fragment loads.
// g_Y[M,2304](fp16) = A'[M,512] @ B'[2304,512]^T  (fp32 accum)
// 128x128 tile, BK=64, 8 warps (warp tile 64x32). 144B-padded smem rows.
// ===========================================================================
#define BK 64
#define TILE_B 18432                  // 128 * 144 bytes per tile buffer

static __device__ __forceinline__ void mma16816(float* c, const uint32_t* a,
                                                const uint32_t* b) {
    asm volatile(
        "mma.sync.aligned.m16n8k16.row.col.f32.f16.f16.f32 "
        "{%0,%1,%2,%3}, {%4,%5,%6,%7}, {%8,%9}, {%0,%1,%2,%3};\n"
        : "+f"(c[0]), "+f"(c[1]), "+f"(c[2]), "+f"(c[3])
        : "r"(a[0]), "r"(a[1]), "r"(a[2]), "r"(a[3]), "r"(b[0]), "r"(b[1]));
}

__global__ __launch_bounds__(256) void k_gemm_mma(int M) {
    extern __shared__ char smem[];   // [A0 | A1 | B0 | B1], each TILE_B bytes
    const uint32_t sbase = s2u(smem);
    const int tid = threadIdx.x;
    const int wid = tid >> 5, lane = tid & 31;
    const int r4 = lane >> 2, q = lane & 3;
    const int rowBase = blockIdx.y * 128;
    const int colBase = blockIdx.x * 128;
    const int wm = (wid >> 2) * 64;      // warp row offset (0 or 64)
    const int wn = (wid & 3) * 32;       // warp col offset (0,32,64,96)

    float acc[4][4][4];
#pragma unroll
    for (int i = 0; i < 4; i++)
#pragma unroll
        for (int j = 0; j < 4; j++)
#pragma unroll
            for (int t = 0; t < 4; t++) acc[i][j][t] = 0.f;

    uint32_t aOff[4];
#pragma unroll
    for (int mi = 0; mi < 4; mi++)
        aOff[mi] = (uint32_t)((wm + mi * 16 + (lane & 15)) * 144 + ((lane >> 4) & 1) * 16);
    uint32_t bOff[2];
#pragma unroll
    for (int p = 0; p < 2; p++)
        bOff[p] = (uint32_t)((wn + p * 16 + ((lane & 16) >> 1) + (lane & 7)) * 144
                             + ((lane >> 3) & 1) * 16);

    auto issueTiles = [&](int kt, int buf) {
        int k0 = kt * BK;
        uint32_t sa = sbase + buf * TILE_B;
        uint32_t sb = sbase + 2 * TILE_B + buf * TILE_B;
#pragma unroll
        for (int i = 0; i < 4; i++) {
            int e = tid + i * 256;
            int r = e >> 3, c8 = e & 7;
            int gr = rowBase + r;
            uint32_t sz = (gr < M) ? 16u : 0u;
            const void* src = &g_Ap[(size_t)(gr < M ? gr : 0) * KK + k0 + c8 * 8];
            asm volatile("cp.async.cg.shared.global [%0], [%1], 16, %2;"
                         :: "r"(sa + r * 144 + c8 * 16), "l"(src), "r"(sz));
        }
#pragma unroll
        for (int i = 0; i < 4; i++) {
            int e = tid + i * 256;
            int r = e >> 3, c8 = e & 7;
            const void* src = &g_Bp[(size_t)(colBase + r) * KK + k0 + c8 * 8];
            asm volatile("cp.async.cg.shared.global [%0], [%1], 16;"
                         :: "r"(sb + r * 144 + c8 * 16), "l"(src));
        }
    };

    const int NT = KK / BK;   // 8
    issueTiles(0, 0);
    CP_COMMIT();

    for (int kt = 0; kt < NT; kt++) {
        int buf = kt & 1;
        if (kt + 1 < NT) {
            issueTiles(kt + 1, buf ^ 1);
            CP_COMMIT();
            CP_WAIT(1);
        } else {
            CP_WAIT(0);
        }
        __syncthreads();

        uint32_t sa = sbase + buf * TILE_B;
        uint32_t sb = sbase + 2 * TILE_B + buf * TILE_B;
#pragma unroll
        for (int ks = 0; ks < 4; ks++) {
            uint32_t af[4][4], bf[2][4];
#pragma unroll
            for (int mi = 0; mi < 4; mi++) LDSM4(af[mi], sa + aOff[mi] + ks * 32);
#pragma unroll
            for (int p = 0; p < 2; p++)    LDSM4(bf[p], sb + bOff[p] + ks * 32);
#pragma unroll
            for (int mi = 0; mi < 4; mi++)
#pragma unroll
                for (int ni = 0; ni < 4; ni++)
                    mma16816(acc[mi][ni], af[mi], &bf[ni >> 1][(ni & 1) * 2]);
        }
        __syncthreads();
    }

    // Epilogue: convert to fp16, write half2 pairs
#pragma unroll
    for (int mi = 0; mi < 4; mi++) {
        int gr0 = rowBase + wm + mi * 16 + r4;
#pragma unroll
        for (int ni = 0; ni < 4; ni++) {
            int gc = colBase + wn + ni * 8 + q * 2;
            if (gr0 < M)
                *(__half2*)&g_Y[(size_t)gr0 * NCOL + gc] =
                    __floats2half2_rn(acc[mi][ni][0], acc[mi][ni][1]);
            if (gr0 + 8 < M)
                *(__half2*)&g_Y[(size_t)(gr0 + 8) * NCOL + gc] =
                    __floats2half2_rn(acc[mi][ni][2], acc[mi][ni][3]);
        }
    }
}

// ===========================================================================
// Expand: H[n,r,o] = sum_b att[r,b] * Y[n, b*256+o]  (fp16 in/out, fp32 math)
// 128 threads per node, each handles a half2 column pair.
__global__ void k_expand(const float* __restrict__ att, int M) {
    int n = blockIdx.x;
    if (n >= M) return;
    int o2 = threadIdx.x;     // 0..127 half2 index
    __shared__ float a[RR][BB];
    a[threadIdx.x >> 3][threadIdx.x & 7] = att[threadIdx.x];   // 128 = RR*BB
    __syncthreads();
    float2 y[BB];
#pragma unroll
    for (int b = 0; b < BB; b++)
        y[b] = __half22float2(*(const __half2*)&g_Y[(size_t)n * NCOL + b * DD + o2 * 2]);
#pragma unroll
    for (int r = 0; r < RR; r++) {
        float sx = 0.f, sy = 0.f;
#pragma unroll
        for (int b = 0; b < BB; b++) {
            sx += a[r][b] * y[b].x;
            sy += a[r][b] * y[b].y;
        }
        *(__half2*)&g_H[((size_t)n * RR + r) * DD + o2 * 2] = __floats2half2_rn(sx, sy);
    }
}

// ===========================================================================
// Edge scatter: agg[dst] += ea * H[src, et]  (one warp per edge, fp16 gather)
__global__ void k_scatter(const int* __restrict__ ei, const int* __restrict__ et,
                          const float* __restrict__ ea, int E) {
    int warp = (blockIdx.x * blockDim.x + threadIdx.x) >> 5;
    int lane = threadIdx.x & 31;
    if (warp >= E) return;
    int src = ei[warp];
    int dst = ei[E + warp];
    int r   = et[warp];
    float w = ea[warp];
    // row = 256 halves = 512B; lane covers halves [lane*8, lane*8+8) via one uint4
    const uint4* h = (const uint4*)&g_H[((size_t)src * RR + r) * DD];
    uint4 v = h[lane];
    const __half2* hp = (const __half2*)&v;
    float4* a = (float4*)&g_agg[(size_t)dst * DD];
    float2 p0 = __half22float2(hp[0]), p1 = __half22float2(hp[1]);
    float2 p2 = __half22float2(hp[2]), p3 = __half22float2(hp[3]);
    asm volatile("red.global.add.v4.f32 [%0], {%1,%2,%3,%4};"
                 :: "l"(a + lane * 2), "f"(p0.x * w), "f"(p0.y * w),
                    "f"(p1.x * w), "f"(p1.y * w) : "memory");
    asm volatile("red.global.add.v4.f32 [%0], {%1,%2,%3,%4};"
                 :: "l"(a + lane * 2 + 1), "f"(p2.x * w), "f"(p2.y * w),
                    "f"(p3.x * w), "f"(p3.y * w) : "memory");
}

// ===========================================================================
// Finalize: val = (agg + H_self)/cnt + Y_root + bias + x; LN; ReLU
// emit_split: write fp16 [hi|lo] split of output into g_Ap for next layer
__global__ void k_finalize(const float* __restrict__ xin, const float* __restrict__ bias,
                           const float* __restrict__ gln, const float* __restrict__ bln,
                           float* __restrict__ out, int M, int emit_split) {
    int n = blockIdx.x;
    if (n >= M) return;
    int o = threadIdx.x;
    size_t no = (size_t)n * DD + o;
    float val = (g_agg[no] + __half2float(g_H[((size_t)n * RR + (RR - 1)) * DD + o])) / g_cnt[n]
              + __half2float(g_Y[(size_t)n * NCOL + BB * DD + o]) + bias[o] + xin[no];

    __shared__ float red[8];
    __shared__ float sh_mu, sh_rstd;
    float s = val;
#pragma unroll
    for (int k = 16; k > 0; k >>= 1) s += __shfl_down_sync(0xffffffffu, s, k);
    if ((o & 31) == 0) red[o >> 5] = s;
    __syncthreads();
    if (o == 0) {
        float t = 0.f;
#pragma unroll
        for (int i = 0; i < 8; i++) t += red[i];
        sh_mu = t * (1.0f / DD);
    }
    __syncthreads();
    float mu = sh_mu;
    float d = val - mu;
    float s2 = d * d;
#pragma unroll
    for (int k = 16; k > 0; k >>= 1) s2 += __shfl_down_sync(0xffffffffu, s2, k);
    if ((o & 31) == 0) red[o >> 5] = s2;
    __syncthreads();
    if (o == 0) {
        float t = 0.f;
#pragma unroll
        for (int i = 0; i < 8; i++) t += red[i];
        sh_rstd = rsqrtf(t * (1.0f / DD) + LN_EPS);
    }
    __syncthreads();
    float y = fmaxf(d * sh_rstd * gln[o] + bln[o], 0.f);
    out[no] = y;
    if (emit_split) {
        __half hi = __float2half_rn(y);
        __half lo = __float2half_rn(y - __half2float(hi));
        size_t base = (size_t)n * KK;
        g_Ap[base + o]       = hi;
        g_Ap[base + 256 + o] = lo;
    }
}

// ===========================================================================
static void run_layer(const float* x, const float* basis, const float* att,
                      const float* root, const float* bias,
                      const float* lg, const float* lb,
                      const int* ei, const int* et, const float* ea,
                      float* out, int M, int E, int emit_split) {
    k_prepw<<<NCOL, 256>>>(basis, root);
    k_zero_agg<<<(M * (DD / 4) + 255) / 256, 256>>>(M);
    {
        dim3 grid(NCOL / 128, (M + 127) / 128);   // (18, 391)
        k_gemm_mma<<<grid, 256, 4 * TILE_B>>>(M);
    }
    k_expand<<<M, 128>>>(att, M);
    k_scatter<<<(E * 32 + 255) / 256, 256>>>(ei, et, ea, E);
    k_finalize<<<M, 256>>>(x, bias, lg, lb, out, M, emit_split);
}

extern "C" void kernel_launch(void* const* d_in, const int* in_sizes, int n_in,
                              void* d_out, int out_size) {
    const float* x   = (const float*)d_in[0];
    const int*   ei  = (const int*)d_in[1];
    const int*   et  = (const int*)d_in[2];
    const float* ea  = (const float*)d_in[3];
    const float* basis1 = (const float*)d_in[4];
    const float* att1   = (const float*)d_in[5];
    const float* root1  = (const float*)d_in[6];
    const float* bias1  = (const float*)d_in[7];
    const float* ln1g   = (const float*)d_in[8];
    const float* ln1b   = (const float*)d_in[9];
    const float* basis2 = (const float*)d_in[10];
    const float* att2   = (const float*)d_in[11];
    const float* root2  = (const float*)d_in[12];
    const float* bias2  = (const float*)d_in[13];
    const float* ln2g   = (const float*)d_in[14];
    const float* ln2b   = (const float*)d_in[15];
    float* out = (float*)d_out;

    int M = in_sizes[0] / DD;     // 50000
    int E = in_sizes[2];          // 800000

    cudaFuncSetAttribute(k_gemm_mma, cudaFuncAttributeMaxDynamicSharedMemorySize,
                         4 * TILE_B);

    void* p = nullptr;
    cudaGetSymbolAddress(&p, g_x1);
    float* x1_dev = (float*)p;

    k_cnt_init<<<(M + 255) / 256, 256>>>(M);
    k_cnt_edges<<<(E + 255) / 256, 256>>>(ei, E);

    // layer 1: split input x; finalize emits split of x1 for layer 2
    k_split_x<<<(M * DD + 255) / 256, 256>>>(x, M);
    run_layer(x, basis1, att1, root1, bias1, ln1g, ln1b, ei, et, ea, x1_dev, M, E, 1);
    // layer 2: g_Ap already populated by layer-1 finalize
    run_layer(x1_dev, basis2, att2, root2, bias2, ln2g, ln2b, ei, et, ea, out, M, E, 0);
}

// round 8
// speedup vs baseline: 2.6771x; 1.2068x over previous
#include <cuda_runtime.h>
#include <cuda_fp16.h>
#include <cstdint>

// Problem constants
#define NN 50000
#define DD 256
#define RR 16
#define BB 8
#define NCOL 2304               // 8 basis blocks + root = 9 * 256
#define KK 256                  // pure fp16 single-product GEMM
#define LN_EPS 1e-5f

// ---- static scratch ----
__device__ __half g_Ap[(size_t)NN * KK];     // fp16 activations [N,256]   25.6MB
__device__ __half g_Bp[(size_t)NCOL * KK];   // fp16 weights [2304,256]     1.2MB
__device__ __half g_Y[(size_t)NN * NCOL];    // x @ W  [N,2304] fp16      230.4MB
__device__ __half g_H[(size_t)NN * RR * DD]; // per-relation fp16         409.6MB
__device__ float g_agg[(size_t)NN * DD];     // edge sums (fp32)           51.2MB
__device__ float g_cnt[NN];                  // indeg + 1
__device__ float g_x1[(size_t)NN * DD];      // layer-1 output

static __device__ __forceinline__ uint32_t s2u(const void* p) {
    uint32_t a;
    asm("{ .reg .u64 t; cvta.to.shared.u64 t, %1; cvt.u32.u64 %0, t; }" : "=r"(a) : "l"(p));
    return a;
}
#define CP_COMMIT() asm volatile("cp.async.commit_group;" ::: "memory")
#define CP_WAIT(n)  asm volatile("cp.async.wait_group %0;" :: "n"(n) : "memory")
#define LDSM4(r, addr) \
    asm volatile("ldmatrix.sync.aligned.m8n8.x4.shared.b16 {%0,%1,%2,%3}, [%4];" \
        : "=r"((r)[0]), "=r"((r)[1]), "=r"((r)[2]), "=r"((r)[3]) : "r"(addr))

// ===========================================================================
// Prep: fp16 weights. Row c of B' = w_hi[., c].
__global__ void k_prepw(const float* __restrict__ basis, const float* __restrict__ root) {
    int c = blockIdx.x;      // 0..2303
    int k = threadIdx.x;     // 0..255
    float w;
    if (c < BB * DD) {
        int b = c >> 8, o = c & 255;
        w = basis[((size_t)b * DD + k) * DD + o];
    } else {
        w = root[(size_t)k * DD + (c - BB * DD)];
    }
    g_Bp[(size_t)c * KK + k] = __float2half_rn(w);
}

// Convert activations to fp16 (layer-1 input only)
__global__ void k_cvt_x(const float* __restrict__ x, int M) {
    int t = blockIdx.x * 256 + threadIdx.x;
    if (t >= M * DD) return;
    g_Ap[t] = __float2half_rn(x[t]);
}

__global__ void k_cnt_init(int M) {
    int n = blockIdx.x * 256 + threadIdx.x;
    if (n < M) g_cnt[n] = 1.0f;
}
__global__ void k_cnt_edges(const int* __restrict__ ei, int E) {
    int t = blockIdx.x * 256 + threadIdx.x;
    if (t < E) atomicAdd(&g_cnt[ei[E + t]], 1.0f);
}
__global__ void k_zero_agg(int M) {
    int t = blockIdx.x * 256 + threadIdx.x;
    if (t < M * (DD / 4)) ((float4*)g_agg)[t] = make_float4(0.f, 0.f, 0.f, 0.f);
}

// ===========================================================================
// fp16 mma.sync GEMM, cp.async double buffering, ldmatrix fragment loads.
// g_Y[M,2304](fp16) = A[M,256] @ B[2304,256]^T  (fp32 accum)
// 128x128 tile, BK=64, 8 warps (warp tile 64x32). 144B-padded smem rows.
// ===========================================================================
#define BK 64
#define TILE_B 18432                  // 128 * 144 bytes per tile buffer

static __device__ __forceinline__ void mma16816(float* c, const uint32_t* a,
                                                const uint32_t* b) {
    asm volatile(
        "mma.sync.aligned.m16n8k16.row.col.f32.f16.f16.f32 "
        "{%0,%1,%2,%3}, {%4,%5,%6,%7}, {%8,%9}, {%0,%1,%2,%3};\n"
        : "+f"(c[0]), "+f"(c[1]), "+f"(c[2]), "+f"(c[3])
        : "r"(a[0]), "r"(a[1]), "r"(a[2]), "r"(a[3]), "r"(b[0]), "r"(b[1]));
}

__global__ __launch_bounds__(256) void k_gemm_mma(int M) {
    extern __shared__ char smem[];   // [A0 | A1 | B0 | B1], each TILE_B bytes
    const uint32_t sbase = s2u(smem);
    const int tid = threadIdx.x;
    const int wid = tid >> 5, lane = tid & 31;
    const int r4 = lane >> 2, q = lane & 3;
    const int rowBase = blockIdx.y * 128;
    const int colBase = blockIdx.x * 128;
    const int wm = (wid >> 2) * 64;      // warp row offset (0 or 64)
    const int wn = (wid & 3) * 32;       // warp col offset (0,32,64,96)

    float acc[4][4][4];
#pragma unroll
    for (int i = 0; i < 4; i++)
#pragma unroll
        for (int j = 0; j < 4; j++)
#pragma unroll
            for (int t = 0; t < 4; t++) acc[i][j][t] = 0.f;

    uint32_t aOff[4];
#pragma unroll
    for (int mi = 0; mi < 4; mi++)
        aOff[mi] = (uint32_t)((wm + mi * 16 + (lane & 15)) * 144 + ((lane >> 4) & 1) * 16);
    uint32_t bOff[2];
#pragma unroll
    for (int p = 0; p < 2; p++)
        bOff[p] = (uint32_t)((wn + p * 16 + ((lane & 16) >> 1) + (lane & 7)) * 144
                             + ((lane >> 3) & 1) * 16);

    auto issueTiles = [&](int kt, int buf) {
        int k0 = kt * BK;
        uint32_t sa = sbase + buf * TILE_B;
        uint32_t sb = sbase + 2 * TILE_B + buf * TILE_B;
#pragma unroll
        for (int i = 0; i < 4; i++) {
            int e = tid + i * 256;
            int r = e >> 3, c8 = e & 7;
            int gr = rowBase + r;
            uint32_t sz = (gr < M) ? 16u : 0u;
            const void* src = &g_Ap[(size_t)(gr < M ? gr : 0) * KK + k0 + c8 * 8];
            asm volatile("cp.async.cg.shared.global [%0], [%1], 16, %2;"
                         :: "r"(sa + r * 144 + c8 * 16), "l"(src), "r"(sz));
        }
#pragma unroll
        for (int i = 0; i < 4; i++) {
            int e = tid + i * 256;
            int r = e >> 3, c8 = e & 7;
            const void* src = &g_Bp[(size_t)(colBase + r) * KK + k0 + c8 * 8];
            asm volatile("cp.async.cg.shared.global [%0], [%1], 16;"
                         :: "r"(sb + r * 144 + c8 * 16), "l"(src));
        }
    };

    const int NT = KK / BK;   // 4
    issueTiles(0, 0);
    CP_COMMIT();

    for (int kt = 0; kt < NT; kt++) {
        int buf = kt & 1;
        if (kt + 1 < NT) {
            issueTiles(kt + 1, buf ^ 1);
            CP_COMMIT();
            CP_WAIT(1);
        } else {
            CP_WAIT(0);
        }
        __syncthreads();

        uint32_t sa = sbase + buf * TILE_B;
        uint32_t sb = sbase + 2 * TILE_B + buf * TILE_B;
#pragma unroll
        for (int ks = 0; ks < 4; ks++) {
            uint32_t af[4][4], bf[2][4];
#pragma unroll
            for (int mi = 0; mi < 4; mi++) LDSM4(af[mi], sa + aOff[mi] + ks * 32);
#pragma unroll
            for (int p = 0; p < 2; p++)    LDSM4(bf[p], sb + bOff[p] + ks * 32);
#pragma unroll
            for (int mi = 0; mi < 4; mi++)
#pragma unroll
                for (int ni = 0; ni < 4; ni++)
                    mma16816(acc[mi][ni], af[mi], &bf[ni >> 1][(ni & 1) * 2]);
        }
        __syncthreads();
    }

    // Epilogue: convert to fp16, write half2 pairs
#pragma unroll
    for (int mi = 0; mi < 4; mi++) {
        int gr0 = rowBase + wm + mi * 16 + r4;
#pragma unroll
        for (int ni = 0; ni < 4; ni++) {
            int gc = colBase + wn + ni * 8 + q * 2;
            if (gr0 < M)
                *(__half2*)&g_Y[(size_t)gr0 * NCOL + gc] =
                    __floats2half2_rn(acc[mi][ni][0], acc[mi][ni][1]);
            if (gr0 + 8 < M)
                *(__half2*)&g_Y[(size_t)(gr0 + 8) * NCOL + gc] =
                    __floats2half2_rn(acc[mi][ni][2], acc[mi][ni][3]);
        }
    }
}

// ===========================================================================
// Expand: H[n,r,o] = sum_b att[r,b] * Y[n, b*256+o]  (fp16 in/out, fp32 math)
__global__ void k_expand(const float* __restrict__ att, int M) {
    int n = blockIdx.x;
    if (n >= M) return;
    int o2 = threadIdx.x;     // 0..127 half2 index
    __shared__ float a[RR][BB];
    a[threadIdx.x >> 3][threadIdx.x & 7] = att[threadIdx.x];   // 128 = RR*BB
    __syncthreads();
    float2 y[BB];
#pragma unroll
    for (int b = 0; b < BB; b++)
        y[b] = __half22float2(*(const __half2*)&g_Y[(size_t)n * NCOL + b * DD + o2 * 2]);
#pragma unroll
    for (int r = 0; r < RR; r++) {
        float sx = 0.f, sy = 0.f;
#pragma unroll
        for (int b = 0; b < BB; b++) {
            sx += a[r][b] * y[b].x;
            sy += a[r][b] * y[b].y;
        }
        *(__half2*)&g_H[((size_t)n * RR + r) * DD + o2 * 2] = __floats2half2_rn(sx, sy);
    }
}

// ===========================================================================
// Edge scatter: agg[dst] += ea * H[src, et]  (one warp per edge, fp16 gather)
__global__ void k_scatter(const int* __restrict__ ei, const int* __restrict__ et,
                          const float* __restrict__ ea, int E) {
    int warp = (blockIdx.x * blockDim.x + threadIdx.x) >> 5;
    int lane = threadIdx.x & 31;
    if (warp >= E) return;
    int src = ei[warp];
    int dst = ei[E + warp];
    int r   = et[warp];
    float w = ea[warp];
    const uint4* h = (const uint4*)&g_H[((size_t)src * RR + r) * DD];
    uint4 v = h[lane];
    const __half2* hp = (const __half2*)&v;
    float4* a = (float4*)&g_agg[(size_t)dst * DD];
    float2 p0 = __half22float2(hp[0]), p1 = __half22float2(hp[1]);
    float2 p2 = __half22float2(hp[2]), p3 = __half22float2(hp[3]);
    asm volatile("red.global.add.v4.f32 [%0], {%1,%2,%3,%4};"
                 :: "l"(a + lane * 2), "f"(p0.x * w), "f"(p0.y * w),
                    "f"(p1.x * w), "f"(p1.y * w) : "memory");
    asm volatile("red.global.add.v4.f32 [%0], {%1,%2,%3,%4};"
                 :: "l"(a + lane * 2 + 1), "f"(p2.x * w), "f"(p2.y * w),
                    "f"(p3.x * w), "f"(p3.y * w) : "memory");
}

// ===========================================================================
// Finalize: val = (agg + H_self)/cnt + Y_root + bias + x; LN; ReLU
// emit_split: write fp16 of output into g_Ap for next layer
__global__ void k_finalize(const float* __restrict__ xin, const float* __restrict__ bias,
                           const float* __restrict__ gln, const float* __restrict__ bln,
                           float* __restrict__ out, int M, int emit_split) {
    int n = blockIdx.x;
    if (n >= M) return;
    int o = threadIdx.x;
    size_t no = (size_t)n * DD + o;
    float val = (g_agg[no] + __half2float(g_H[((size_t)n * RR + (RR - 1)) * DD + o])) / g_cnt[n]
              + __half2float(g_Y[(size_t)n * NCOL + BB * DD + o]) + bias[o] + xin[no];

    __shared__ float red[8];
    __shared__ float sh_mu, sh_rstd;
    float s = val;
#pragma unroll
    for (int k = 16; k > 0; k >>= 1) s += __shfl_down_sync(0xffffffffu, s, k);
    if ((o & 31) == 0) red[o >> 5] = s;
    __syncthreads();
    if (o == 0) {
        float t = 0.f;
#pragma unroll
        for (int i = 0; i < 8; i++) t += red[i];
        sh_mu = t * (1.0f / DD);
    }
    __syncthreads();
    float mu = sh_mu;
    float d = val - mu;
    float s2 = d * d;
#pragma unroll
    for (int k = 16; k > 0; k >>= 1) s2 += __shfl_down_sync(0xffffffffu, s2, k);
    if ((o & 31) == 0) red[o >> 5] = s2;
    __syncthreads();
    if (o == 0) {
        float t = 0.f;
#pragma unroll
        for (int i = 0; i < 8; i++) t += red[i];
        sh_rstd = rsqrtf(t * (1.0f / DD) + LN_EPS);
    }
    __syncthreads();
    float y = fmaxf(d * sh_rstd * gln[o] + bln[o], 0.f);
    out[no] = y;
    if (emit_split) g_Ap[no] = __float2half_rn(y);
}

// ===========================================================================
static void run_layer(const float* x, const float* basis, const float* att,
                      const float* root, const float* bias,
                      const float* lg, const float* lb,
                      const int* ei, const int* et, const float* ea,
                      float* out, int M, int E, int emit_split) {
    k_prepw<<<NCOL, 256>>>(basis, root);
    k_zero_agg<<<(M * (DD / 4) + 255) / 256, 256>>>(M);
    {
        dim3 grid(NCOL / 128, (M + 127) / 128);   // (18, 391)
        k_gemm_mma<<<grid, 256, 4 * TILE_B>>>(M);
    }
    k_expand<<<M, 128>>>(att, M);
    k_scatter<<<(E * 32 + 255) / 256, 256>>>(ei, et, ea, E);
    k_finalize<<<M, 256>>>(x, bias, lg, lb, out, M, emit_split);
}

extern "C" void kernel_launch(void* const* d_in, const int* in_sizes, int n_in,
                              void* d_out, int out_size) {
    const float* x   = (const float*)d_in[0];
    const int*   ei  = (const int*)d_in[1];
    const int*   et  = (const int*)d_in[2];
    const float* ea  = (const float*)d_in[3];
    const float* basis1 = (const float*)d_in[4];
    const float* att1   = (const float*)d_in[5];
    const float* root1  = (const float*)d_in[6];
    const float* bias1  = (const float*)d_in[7];
    const float* ln1g   = (const float*)d_in[8];
    const float* ln1b   = (const float*)d_in[9];
    const float* basis2 = (const float*)d_in[10];
    const float* att2   = (const float*)d_in[11];
    const float* root2  = (const float*)d_in[12];
    const float* bias2  = (const float*)d_in[13];
    const float* ln2g   = (const float*)d_in[14];
    const float* ln2b   = (const float*)d_in[15];
    float* out = (float*)d_out;

    int M = in_sizes[0] / DD;     // 50000
    int E = in_sizes[2];          // 800000

    cudaFuncSetAttribute(k_gemm_mma, cudaFuncAttributeMaxDynamicSharedMemorySize,
                         4 * TILE_B);

    void* p = nullptr;
    cudaGetSymbolAddress(&p, g_x1);
    float* x1_dev = (float*)p;

    k_cnt_init<<<(M + 255) / 256, 256>>>(M);
    k_cnt_edges<<<(E + 255) / 256, 256>>>(ei, E);

    // layer 1: convert input to fp16; finalize emits fp16 x1 for layer 2
    k_cvt_x<<<(M * DD + 255) / 256, 256>>>(x, M);
    run_layer(x, basis1, att1, root1, bias1, ln1g, ln1b, ei, et, ea, x1_dev, M, E, 1);
    // layer 2: g_Ap already populated by layer-1 finalize
    run_layer(x1_dev, basis2, att2, root2, bias2, ln2g, ln2b, ei, et, ea, out, M, E, 0);
}

// round 10
// speedup vs baseline: 3.9956x; 1.4925x over previous
#include <cuda_runtime.h>
#include <cuda_fp16.h>
#include <cstdint>

// Problem constants
#define NN 50000
#define DD 256
#define RR 16
#define BB 8
#define NCOL 2304               // 8 basis blocks + root = 9 * 256
#define KK 256                  // pure fp16 single-product GEMM
#define EE 800000
#define LN_EPS 1e-5f

// ---- static scratch ----
__device__ __half g_Ap[(size_t)NN * KK];     // fp16 activations [N,256]
__device__ __half g_Bp[(size_t)NCOL * KK];   // fp16 weights [2304,256]
__device__ __half g_Y[(size_t)NN * NCOL];    // x @ W  [N,2304] fp16
__device__ __half g_H[(size_t)NN * RR * DD]; // per-relation fp16
__device__ float g_x1[(size_t)NN * DD];      // layer-1 output
// CSR over dst
__device__ int g_deg[NN];
__device__ int g_rowptr[NN];
__device__ int g_bsum[256];
__device__ int g_fill[NN];
__device__ uint32_t g_epack[EE];             // src | (et << 16)
__device__ float g_ew[EE];

static __device__ __forceinline__ uint32_t s2u(const void* p) {
    uint32_t a;
    asm("{ .reg .u64 t; cvta.to.shared.u64 t, %1; cvt.u32.u64 %0, t; }" : "=r"(a) : "l"(p));
    return a;
}
#define CP_COMMIT() asm volatile("cp.async.commit_group;" ::: "memory")
#define CP_WAIT(n)  asm volatile("cp.async.wait_group %0;" :: "n"(n) : "memory")
#define LDSM4(r, addr) \
    asm volatile("ldmatrix.sync.aligned.m8n8.x4.shared.b16 {%0,%1,%2,%3}, [%4];" \
        : "=r"((r)[0]), "=r"((r)[1]), "=r"((r)[2]), "=r"((r)[3]) : "r"(addr))

// ===========================================================================
// CSR build
__global__ void k_zero_degfill(int M) {
    int t = blockIdx.x * 256 + threadIdx.x;
    if (t < M) { g_deg[t] = 0; g_fill[t] = 0; }
}
__global__ void k_deg_count(const int* __restrict__ ei, int E) {
    int t = blockIdx.x * 256 + threadIdx.x;
    if (t < E) atomicAdd(&g_deg[ei[E + t]], 1);
}
__global__ void k_scan1(int M) {
    __shared__ int s[256];
    int i = blockIdx.x * 256 + threadIdx.x;
    int v = (i < M) ? g_deg[i] : 0;
    s[threadIdx.x] = v;
    __syncthreads();
    for (int off = 1; off < 256; off <<= 1) {
        int t = (threadIdx.x >= off) ? s[threadIdx.x - off] : 0;
        __syncthreads();
        s[threadIdx.x] += t;
        __syncthreads();
    }
    if (i < M) g_rowptr[i] = s[threadIdx.x] - v;      // block-local exclusive
    if (threadIdx.x == 255) g_bsum[blockIdx.x] = s[255];
}
__global__ void k_scan2(int nb) {   // 1 block, nb <= 256
    __shared__ int s[256];
    int v = (threadIdx.x < nb) ? g_bsum[threadIdx.x] : 0;
    s[threadIdx.x] = v;
    __syncthreads();
    for (int off = 1; off < 256; off <<= 1) {
        int t = (threadIdx.x >= off) ? s[threadIdx.x - off] : 0;
        __syncthreads();
        s[threadIdx.x] += t;
        __syncthreads();
    }
    g_bsum[threadIdx.x] = s[threadIdx.x] - v;          // exclusive block offsets
}
__global__ void k_scan3(int M) {
    int i = blockIdx.x * 256 + threadIdx.x;
    if (i < M) g_rowptr[i] += g_bsum[i >> 8];
}
__global__ void k_fill(const int* __restrict__ ei, const int* __restrict__ et,
                       const float* __restrict__ ea, int E) {
    int t = blockIdx.x * 256 + threadIdx.x;
    if (t >= E) return;
    int dst = ei[E + t];
    int slot = atomicAdd(&g_fill[dst], 1);
    int idx = g_rowptr[dst] + slot;
    g_epack[idx] = (uint32_t)ei[t] | ((uint32_t)et[t] << 16);
    g_ew[idx] = ea[t];
}

// ===========================================================================
// Prep: fp16 weights
__global__ void k_prepw(const float* __restrict__ basis, const float* __restrict__ root) {
    int c = blockIdx.x;      // 0..2303
    int k = threadIdx.x;     // 0..255
    float w;
    if (c < BB * DD) {
        int b = c >> 8, o = c & 255;
        w = basis[((size_t)b * DD + k) * DD + o];
    } else {
        w = root[(size_t)k * DD + (c - BB * DD)];
    }
    g_Bp[(size_t)c * KK + k] = __float2half_rn(w);
}
__global__ void k_cvt_x(const float* __restrict__ x, int M) {
    int t = blockIdx.x * 256 + threadIdx.x;
    if (t >= M * DD) return;
    g_Ap[t] = __float2half_rn(x[t]);
}

// ===========================================================================
// fp16 mma.sync GEMM (unchanged from R8)
#define BK 64
#define TILE_B 18432

static __device__ __forceinline__ void mma16816(float* c, const uint32_t* a,
                                                const uint32_t* b) {
    asm volatile(
        "mma.sync.aligned.m16n8k16.row.col.f32.f16.f16.f32 "
        "{%0,%1,%2,%3}, {%4,%5,%6,%7}, {%8,%9}, {%0,%1,%2,%3};\n"
        : "+f"(c[0]), "+f"(c[1]), "+f"(c[2]), "+f"(c[3])
        : "r"(a[0]), "r"(a[1]), "r"(a[2]), "r"(a[3]), "r"(b[0]), "r"(b[1]));
}

__global__ __launch_bounds__(256) void k_gemm_mma(int M) {
    extern __shared__ char smem[];
    const uint32_t sbase = s2u(smem);
    const int tid = threadIdx.x;
    const int wid = tid >> 5, lane = tid & 31;
    const int r4 = lane >> 2, q = lane & 3;
    const int rowBase = blockIdx.y * 128;
    const int colBase = blockIdx.x * 128;
    const int wm = (wid >> 2) * 64;
    const int wn = (wid & 3) * 32;

    float acc[4][4][4];
#pragma unroll
    for (int i = 0; i < 4; i++)
#pragma unroll
        for (int j = 0; j < 4; j++)
#pragma unroll
            for (int t = 0; t < 4; t++) acc[i][j][t] = 0.f;

    uint32_t aOff[4];
#pragma unroll
    for (int mi = 0; mi < 4; mi++)
        aOff[mi] = (uint32_t)((wm + mi * 16 + (lane & 15)) * 144 + ((lane >> 4) & 1) * 16);
    uint32_t bOff[2];
#pragma unroll
    for (int p = 0; p < 2; p++)
        bOff[p] = (uint32_t)((wn + p * 16 + ((lane & 16) >> 1) + (lane & 7)) * 144
                             + ((lane >> 3) & 1) * 16);

    auto issueTiles = [&](int kt, int buf) {
        int k0 = kt * BK;
        uint32_t sa = sbase + buf * TILE_B;
        uint32_t sb = sbase + 2 * TILE_B + buf * TILE_B;
#pragma unroll
        for (int i = 0; i < 4; i++) {
            int e = tid + i * 256;
            int r = e >> 3, c8 = e & 7;
            int gr = rowBase + r;
            uint32_t sz = (gr < M) ? 16u : 0u;
            const void* src = &g_Ap[(size_t)(gr < M ? gr : 0) * KK + k0 + c8 * 8];
            asm volatile("cp.async.cg.shared.global [%0], [%1], 16, %2;"
                         :: "r"(sa + r * 144 + c8 * 16), "l"(src), "r"(sz));
        }
#pragma unroll
        for (int i = 0; i < 4; i++) {
            int e = tid + i * 256;
            int r = e >> 3, c8 = e & 7;
            const void* src = &g_Bp[(size_t)(colBase + r) * KK + k0 + c8 * 8];
            asm volatile("cp.async.cg.shared.global [%0], [%1], 16;"
                         :: "r"(sb + r * 144 + c8 * 16), "l"(src));
        }
    };

    const int NT = KK / BK;   // 4
    issueTiles(0, 0);
    CP_COMMIT();

    for (int kt = 0; kt < NT; kt++) {
        int buf = kt & 1;
        if (kt + 1 < NT) {
            issueTiles(kt + 1, buf ^ 1);
            CP_COMMIT();
            CP_WAIT(1);
        } else {
            CP_WAIT(0);
        }
        __syncthreads();

        uint32_t sa = sbase + buf * TILE_B;
        uint32_t sb = sbase + 2 * TILE_B + buf * TILE_B;
#pragma unroll
        for (int ks = 0; ks < 4; ks++) {
            uint32_t af[4][4], bf[2][4];
#pragma unroll
            for (int mi = 0; mi < 4; mi++) LDSM4(af[mi], sa + aOff[mi] + ks * 32);
#pragma unroll
            for (int p = 0; p < 2; p++)    LDSM4(bf[p], sb + bOff[p] + ks * 32);
#pragma unroll
            for (int mi = 0; mi < 4; mi++)
#pragma unroll
                for (int ni = 0; ni < 4; ni++)
                    mma16816(acc[mi][ni], af[mi], &bf[ni >> 1][(ni & 1) * 2]);
        }
        __syncthreads();
    }

#pragma unroll
    for (int mi = 0; mi < 4; mi++) {
        int gr0 = rowBase + wm + mi * 16 + r4;
#pragma unroll
        for (int ni = 0; ni < 4; ni++) {
            int gc = colBase + wn + ni * 8 + q * 2;
            if (gr0 < M)
                *(__half2*)&g_Y[(size_t)gr0 * NCOL + gc] =
                    __floats2half2_rn(acc[mi][ni][0], acc[mi][ni][1]);
            if (gr0 + 8 < M)
                *(__half2*)&g_Y[(size_t)(gr0 + 8) * NCOL + gc] =
                    __floats2half2_rn(acc[mi][ni][2], acc[mi][ni][3]);
        }
    }
}

// ===========================================================================
// Expand: H[n,r,o] = sum_b att[r,b] * Y[n, b*256+o]
__global__ void k_expand(const float* __restrict__ att, int M) {
    int n = blockIdx.x;
    if (n >= M) return;
    int o2 = threadIdx.x;     // 0..127 half2 index
    __shared__ float a[RR][BB];
    a[threadIdx.x >> 3][threadIdx.x & 7] = att[threadIdx.x];
    __syncthreads();
    float2 y[BB];
#pragma unroll
    for (int b = 0; b < BB; b++)
        y[b] = __half22float2(*(const __half2*)&g_Y[(size_t)n * NCOL + b * DD + o2 * 2]);
#pragma unroll
    for (int r = 0; r < RR; r++) {
        float sx = 0.f, sy = 0.f;
#pragma unroll
        for (int b = 0; b < BB; b++) {
            sx += a[r][b] * y[b].x;
            sy += a[r][b] * y[b].y;
        }
        *(__half2*)&g_H[((size_t)n * RR + r) * DD + o2 * 2] = __floats2half2_rn(sx, sy);
    }
}

// ===========================================================================
// Fused gather + finalize: one warp per dst node; no atomics.
// acc = H[n,R-1] + sum_edges w*H[src,r]; val = acc/cnt + Y_root + bias + x;
// LayerNorm (warp shuffles) + ReLU; write out (+ fp16 for next layer GEMM).
__global__ __launch_bounds__(256) void k_gather_fin(
    const float* __restrict__ xin, const float* __restrict__ bias,
    const float* __restrict__ gln, const float* __restrict__ bln,
    float* __restrict__ out, int M, int emit_split) {
    int wid = threadIdx.x >> 5, lane = threadIdx.x & 31;
    int n = blockIdx.x * 8 + wid;
    if (n >= M) return;
    int start = g_rowptr[n];
    int deg = g_deg[n];

    float acc[8];
    {
        const uint4* hs = (const uint4*)&g_H[((size_t)n * RR + (RR - 1)) * DD];
        uint4 v = hs[lane];
        const __half2* hp = (const __half2*)&v;
#pragma unroll
        for (int j = 0; j < 4; j++) {
            float2 p = __half22float2(hp[j]);
            acc[2 * j] = p.x; acc[2 * j + 1] = p.y;
        }
    }
    for (int i = start; i < start + deg; i++) {
        uint32_t pk = g_epack[i];
        float w = g_ew[i];
        int src = pk & 0xFFFF;
        int r = pk >> 16;
        const uint4* h = (const uint4*)&g_H[((size_t)src * RR + r) * DD];
        uint4 u = h[lane];
        const __half2* up = (const __half2*)&u;
#pragma unroll
        for (int j = 0; j < 4; j++) {
            float2 p = __half22float2(up[j]);
            acc[2 * j]     += w * p.x;
            acc[2 * j + 1] += w * p.y;
        }
    }
    float inv = 1.0f / (float)(deg + 1);
    size_t no = (size_t)n * DD + lane * 8;
    int c0 = lane * 8;

    uint4 yv = *(const uint4*)&g_Y[(size_t)n * NCOL + BB * DD + c0];
    const __half2* yp = (const __half2*)&yv;
    float4 xv0 = *(const float4*)&xin[no];
    float4 xv1 = *(const float4*)&xin[no + 4];
    float4 bv0 = *(const float4*)&bias[c0];
    float4 bv1 = *(const float4*)&bias[c0 + 4];

    float val[8];
    {
        float2 y0 = __half22float2(yp[0]), y1 = __half22float2(yp[1]);
        float2 y2 = __half22float2(yp[2]), y3 = __half22float2(yp[3]);
        val[0] = acc[0] * inv + y0.x + bv0.x + xv0.x;
        val[1] = acc[1] * inv + y0.y + bv0.y + xv0.y;
        val[2] = acc[2] * inv + y1.x + bv0.z + xv0.z;
        val[3] = acc[3] * inv + y1.y + bv0.w + xv0.w;
        val[4] = acc[4] * inv + y2.x + bv1.x + xv1.x;
        val[5] = acc[5] * inv + y2.y + bv1.y + xv1.y;
        val[6] = acc[6] * inv + y3.x + bv1.z + xv1.z;
        val[7] = acc[7] * inv + y3.y + bv1.w + xv1.w;
    }
    // LayerNorm over the 256 values held by this warp
    float s = 0.f;
#pragma unroll
    for (int j = 0; j < 8; j++) s += val[j];
#pragma unroll
    for (int k = 16; k > 0; k >>= 1) s += __shfl_xor_sync(0xffffffffu, s, k);
    float mu = s * (1.0f / DD);
    float s2 = 0.f;
#pragma unroll
    for (int j = 0; j < 8; j++) { float d = val[j] - mu; s2 += d * d; }
#pragma unroll
    for (int k = 16; k > 0; k >>= 1) s2 += __shfl_xor_sync(0xffffffffu, s2, k);
    float rstd = rsqrtf(s2 * (1.0f / DD) + LN_EPS);

    float4 gv0 = *(const float4*)&gln[c0];
    float4 gv1 = *(const float4*)&gln[c0 + 4];
    float4 lb0 = *(const float4*)&bln[c0];
    float4 lb1 = *(const float4*)&bln[c0 + 4];
    float y[8];
    y[0] = fmaxf((val[0] - mu) * rstd * gv0.x + lb0.x, 0.f);
    y[1] = fmaxf((val[1] - mu) * rstd * gv0.y + lb0.y, 0.f);
    y[2] = fmaxf((val[2] - mu) * rstd * gv0.z + lb0.z, 0.f);
    y[3] = fmaxf((val[3] - mu) * rstd * gv0.w + lb0.w, 0.f);
    y[4] = fmaxf((val[4] - mu) * rstd * gv1.x + lb1.x, 0.f);
    y[5] = fmaxf((val[5] - mu) * rstd * gv1.y + lb1.y, 0.f);
    y[6] = fmaxf((val[6] - mu) * rstd * gv1.z + lb1.z, 0.f);
    y[7] = fmaxf((val[7] - mu) * rstd * gv1.w + lb1.w, 0.f);

    *(float4*)&out[no]     = make_float4(y[0], y[1], y[2], y[3]);
    *(float4*)&out[no + 4] = make_float4(y[4], y[5], y[6], y[7]);
    if (emit_split) {
        uint4 hv;
        __half2* hp = (__half2*)&hv;
        hp[0] = __floats2half2_rn(y[0], y[1]);
        hp[1] = __floats2half2_rn(y[2], y[3]);
        hp[2] = __floats2half2_rn(y[4], y[5]);
        hp[3] = __floats2half2_rn(y[6], y[7]);
        *(uint4*)&g_Ap[(size_t)n * KK + c0] = hv;
    }
}

// ===========================================================================
static void run_layer(const float* x, const float* basis, const float* att,
                      const float* root, const float* bias,
                      const float* lg, const float* lb,
                      float* out, int M, int emit_split) {
    k_prepw<<<NCOL, 256>>>(basis, root);
    {
        dim3 grid(NCOL / 128, (M + 127) / 128);   // (18, 391)
        k_gemm_mma<<<grid, 256, 4 * TILE_B>>>(M);
    }
    k_expand<<<M, 128>>>(att, M);
    k_gather_fin<<<(M + 7) / 8, 256>>>(x, bias, lg, lb, out, M, emit_split);
}

extern "C" void kernel_launch(void* const* d_in, const int* in_sizes, int n_in,
                              void* d_out, int out_size) {
    const float* x   = (const float*)d_in[0];
    const int*   ei  = (const int*)d_in[1];
    const int*   et  = (const int*)d_in[2];
    const float* ea  = (const float*)d_in[3];
    const float* basis1 = (const float*)d_in[4];
    const float* att1   = (const float*)d_in[5];
    const float* root1  = (const float*)d_in[6];
    const float* bias1  = (const float*)d_in[7];
    const float* ln1g   = (const float*)d_in[8];
    const float* ln1b   = (const float*)d_in[9];
    const float* basis2 = (const float*)d_in[10];
    const float* att2   = (const float*)d_in[11];
    const float* root2  = (const float*)d_in[12];
    const float* bias2  = (const float*)d_in[13];
    const float* ln2g   = (const float*)d_in[14];
    const float* ln2b   = (const float*)d_in[15];
    float* out = (float*)d_out;

    int M = in_sizes[0] / DD;     // 50000
    int E = in_sizes[2];          // 800000

    cudaFuncSetAttribute(k_gemm_mma, cudaFuncAttributeMaxDynamicSharedMemorySize,
                         4 * TILE_B);

    void* p = nullptr;
    cudaGetSymbolAddress(&p, g_x1);
    float* x1_dev = (float*)p;

    // CSR over dst (shared by both layers)
    int nb = (M + 255) / 256;                  // 196
    k_zero_degfill<<<nb, 256>>>(M);
    k_deg_count<<<(E + 255) / 256, 256>>>(ei, E);
    k_scan1<<<nb, 256>>>(M);
    k_scan2<<<1, 256>>>(nb);
    k_scan3<<<nb, 256>>>(M);
    k_fill<<<(E + 255) / 256, 256>>>(ei, et, ea, E);

    // layer 1
    k_cvt_x<<<(M * DD + 255) / 256, 256>>>(x, M);
    run_layer(x, basis1, att1, root1, bias1, ln1g, ln1b, x1_dev, M, 1);
    // layer 2 (g_Ap emitted by layer-1 gather_fin)
    run_layer(x1_dev, basis2, att2, root2, bias2, ln2g, ln2b, out, M, 0);
}

// round 11
// speedup vs baseline: 4.1246x; 1.0323x over previous
#include <cuda_runtime.h>
#include <cuda_fp16.h>
#include <cstdint>

// Problem constants
#define NN 50000
#define DD 256
#define RR 16
#define BB 8
#define NCOL 2304               // 8 basis blocks + root = 9 * 256
#define KK 256                  // pure fp16 single-product GEMM
#define EE 800000
#define LN_EPS 1e-5f

// ---- static scratch ----
__device__ __half g_Ap[(size_t)NN * KK];     // fp16 activations [N,256]
__device__ __half g_Bp[(size_t)NCOL * KK];   // fp16 weights [2304,256]
__device__ __half g_Y[(size_t)NN * NCOL];    // x @ W  [N,2304] fp16
__device__ __half g_H[(size_t)NN * RR * DD]; // per-relation fp16
__device__ float g_x1[(size_t)NN * DD];      // layer-1 output
// CSR over dst
__device__ int g_deg[NN];
__device__ int g_rowptr[NN];
__device__ int g_bsum[256];
__device__ int g_fill[NN];
__device__ uint32_t g_epack[EE];             // src | (et << 16)
__device__ float g_ew[EE];

static __device__ __forceinline__ uint32_t s2u(const void* p) {
    uint32_t a;
    asm("{ .reg .u64 t; cvta.to.shared.u64 t, %1; cvt.u32.u64 %0, t; }" : "=r"(a) : "l"(p));
    return a;
}
#define CP_COMMIT() asm volatile("cp.async.commit_group;" ::: "memory")
#define CP_WAIT(n)  asm volatile("cp.async.wait_group %0;" :: "n"(n) : "memory")
#define LDSM4(r, addr) \
    asm volatile("ldmatrix.sync.aligned.m8n8.x4.shared.b16 {%0,%1,%2,%3}, [%4];" \
        : "=r"((r)[0]), "=r"((r)[1]), "=r"((r)[2]), "=r"((r)[3]) : "r"(addr))

// ===========================================================================
// CSR build
__global__ void k_zero_degfill(int M) {
    int t = blockIdx.x * 256 + threadIdx.x;
    if (t < M) { g_deg[t] = 0; g_fill[t] = 0; }
}
__global__ void k_deg_count(const int* __restrict__ ei, int E) {
    int t = blockIdx.x * 256 + threadIdx.x;
    if (t < E) atomicAdd(&g_deg[ei[E + t]], 1);
}
__global__ void k_scan1(int M) {
    __shared__ int s[256];
    int i = blockIdx.x * 256 + threadIdx.x;
    int v = (i < M) ? g_deg[i] : 0;
    s[threadIdx.x] = v;
    __syncthreads();
    for (int off = 1; off < 256; off <<= 1) {
        int t = (threadIdx.x >= off) ? s[threadIdx.x - off] : 0;
        __syncthreads();
        s[threadIdx.x] += t;
        __syncthreads();
    }
    if (i < M) g_rowptr[i] = s[threadIdx.x] - v;      // block-local exclusive
    if (threadIdx.x == 255) g_bsum[blockIdx.x] = s[255];
}
__global__ void k_scan2(int nb) {   // 1 block, nb <= 256
    __shared__ int s[256];
    int v = (threadIdx.x < nb) ? g_bsum[threadIdx.x] : 0;
    s[threadIdx.x] = v;
    __syncthreads();
    for (int off = 1; off < 256; off <<= 1) {
        int t = (threadIdx.x >= off) ? s[threadIdx.x - off] : 0;
        __syncthreads();
        s[threadIdx.x] += t;
        __syncthreads();
    }
    g_bsum[threadIdx.x] = s[threadIdx.x] - v;          // exclusive block offsets
}
__global__ void k_scan3(int M) {
    int i = blockIdx.x * 256 + threadIdx.x;
    if (i < M) g_rowptr[i] += g_bsum[i >> 8];
}
__global__ void k_fill(const int* __restrict__ ei, const int* __restrict__ et,
                       const float* __restrict__ ea, int E) {
    int t = blockIdx.x * 256 + threadIdx.x;
    if (t >= E) return;
    int dst = ei[E + t];
    int slot = atomicAdd(&g_fill[dst], 1);
    int idx = g_rowptr[dst] + slot;
    g_epack[idx] = (uint32_t)ei[t] | ((uint32_t)et[t] << 16);
    g_ew[idx] = ea[t];
}

// ===========================================================================
// Prep: fp16 weights
__global__ void k_prepw(const float* __restrict__ basis, const float* __restrict__ root) {
    int c = blockIdx.x;      // 0..2303
    int k = threadIdx.x;     // 0..255
    float w;
    if (c < BB * DD) {
        int b = c >> 8, o = c & 255;
        w = basis[((size_t)b * DD + k) * DD + o];
    } else {
        w = root[(size_t)k * DD + (c - BB * DD)];
    }
    g_Bp[(size_t)c * KK + k] = __float2half_rn(w);
}
__global__ void k_cvt_x(const float* __restrict__ x, int M) {
    int t = blockIdx.x * 256 + threadIdx.x;
    if (t >= M * DD) return;
    g_Ap[t] = __float2half_rn(x[t]);
}

// ===========================================================================
// fp16 mma.sync GEMM (R8 core, pinned 2 CTAs/SM)
#define BK 64
#define TILE_B 18432

static __device__ __forceinline__ void mma16816(float* c, const uint32_t* a,
                                                const uint32_t* b) {
    asm volatile(
        "mma.sync.aligned.m16n8k16.row.col.f32.f16.f16.f32 "
        "{%0,%1,%2,%3}, {%4,%5,%6,%7}, {%8,%9}, {%0,%1,%2,%3};\n"
        : "+f"(c[0]), "+f"(c[1]), "+f"(c[2]), "+f"(c[3])
        : "r"(a[0]), "r"(a[1]), "r"(a[2]), "r"(a[3]), "r"(b[0]), "r"(b[1]));
}

__global__ __launch_bounds__(256, 2) void k_gemm_mma(int M) {
    extern __shared__ char smem[];
    const uint32_t sbase = s2u(smem);
    const int tid = threadIdx.x;
    const int wid = tid >> 5, lane = tid & 31;
    const int r4 = lane >> 2, q = lane & 3;
    const int rowBase = blockIdx.y * 128;
    const int colBase = blockIdx.x * 128;
    const int wm = (wid >> 2) * 64;
    const int wn = (wid & 3) * 32;

    float acc[4][4][4];
#pragma unroll
    for (int i = 0; i < 4; i++)
#pragma unroll
        for (int j = 0; j < 4; j++)
#pragma unroll
            for (int t = 0; t < 4; t++) acc[i][j][t] = 0.f;

    uint32_t aOff[4];
#pragma unroll
    for (int mi = 0; mi < 4; mi++)
        aOff[mi] = (uint32_t)((wm + mi * 16 + (lane & 15)) * 144 + ((lane >> 4) & 1) * 16);
    uint32_t bOff[2];
#pragma unroll
    for (int p = 0; p < 2; p++)
        bOff[p] = (uint32_t)((wn + p * 16 + ((lane & 16) >> 1) + (lane & 7)) * 144
                             + ((lane >> 3) & 1) * 16);

    auto issueTiles = [&](int kt, int buf) {
        int k0 = kt * BK;
        uint32_t sa = sbase + buf * TILE_B;
        uint32_t sb = sbase + 2 * TILE_B + buf * TILE_B;
#pragma unroll
        for (int i = 0; i < 4; i++) {
            int e = tid + i * 256;
            int r = e >> 3, c8 = e & 7;
            int gr = rowBase + r;
            uint32_t sz = (gr < M) ? 16u : 0u;
            const void* src = &g_Ap[(size_t)(gr < M ? gr : 0) * KK + k0 + c8 * 8];
            asm volatile("cp.async.cg.shared.global [%0], [%1], 16, %2;"
                         :: "r"(sa + r * 144 + c8 * 16), "l"(src), "r"(sz));
        }
#pragma unroll
        for (int i = 0; i < 4; i++) {
            int e = tid + i * 256;
            int r = e >> 3, c8 = e & 7;
            const void* src = &g_Bp[(size_t)(colBase + r) * KK + k0 + c8 * 8];
            asm volatile("cp.async.cg.shared.global [%0], [%1], 16;"
                         :: "r"(sb + r * 144 + c8 * 16), "l"(src));
        }
    };

    const int NT = KK / BK;   // 4
    issueTiles(0, 0);
    CP_COMMIT();

    for (int kt = 0; kt < NT; kt++) {
        int buf = kt & 1;
        if (kt + 1 < NT) {
            issueTiles(kt + 1, buf ^ 1);
            CP_COMMIT();
            CP_WAIT(1);
        } else {
            CP_WAIT(0);
        }
        __syncthreads();

        uint32_t sa = sbase + buf * TILE_B;
        uint32_t sb = sbase + 2 * TILE_B + buf * TILE_B;
#pragma unroll
        for (int ks = 0; ks < 4; ks++) {
            uint32_t af[4][4], bf[2][4];
#pragma unroll
            for (int mi = 0; mi < 4; mi++) LDSM4(af[mi], sa + aOff[mi] + ks * 32);
#pragma unroll
            for (int p = 0; p < 2; p++)    LDSM4(bf[p], sb + bOff[p] + ks * 32);
#pragma unroll
            for (int mi = 0; mi < 4; mi++)
#pragma unroll
                for (int ni = 0; ni < 4; ni++)
                    mma16816(acc[mi][ni], af[mi], &bf[ni >> 1][(ni & 1) * 2]);
        }
        __syncthreads();
    }

#pragma unroll
    for (int mi = 0; mi < 4; mi++) {
        int gr0 = rowBase + wm + mi * 16 + r4;
#pragma unroll
        for (int ni = 0; ni < 4; ni++) {
            int gc = colBase + wn + ni * 8 + q * 2;
            if (gr0 < M)
                *(__half2*)&g_Y[(size_t)gr0 * NCOL + gc] =
                    __floats2half2_rn(acc[mi][ni][0], acc[mi][ni][1]);
            if (gr0 + 8 < M)
                *(__half2*)&g_Y[(size_t)(gr0 + 8) * NCOL + gc] =
                    __floats2half2_rn(acc[mi][ni][2], acc[mi][ni][3]);
        }
    }
}

// ===========================================================================
// Expand: H[n,r,o] = sum_b att[r,b] * Y[n, b*256+o]
// One warp per node; lane covers 8 cols; all IO as uint4 (16B).
__global__ __launch_bounds__(256) void k_expand(const float* __restrict__ att, int M) {
    __shared__ float a[RR * BB];
    if (threadIdx.x < RR * BB) a[threadIdx.x] = att[threadIdx.x];
    __syncthreads();
    int n = blockIdx.x * 8 + (threadIdx.x >> 5);
    if (n >= M) return;
    int lane = threadIdx.x & 31;
    int c0 = lane * 8;
    float y[BB][8];
#pragma unroll
    for (int b = 0; b < BB; b++) {
        uint4 v = *(const uint4*)&g_Y[(size_t)n * NCOL + b * DD + c0];
        const __half2* hp = (const __half2*)&v;
#pragma unroll
        for (int j = 0; j < 4; j++) {
            float2 p = __half22float2(hp[j]);
            y[b][2 * j] = p.x; y[b][2 * j + 1] = p.y;
        }
    }
#pragma unroll
    for (int r = 0; r < RR; r++) {
        float o[8] = {0.f, 0.f, 0.f, 0.f, 0.f, 0.f, 0.f, 0.f};
#pragma unroll
        for (int b = 0; b < BB; b++) {
            float ab = a[r * BB + b];
#pragma unroll
            for (int j = 0; j < 8; j++) o[j] += ab * y[b][j];
        }
        uint4 hv;
        __half2* hp = (__half2*)&hv;
        hp[0] = __floats2half2_rn(o[0], o[1]);
        hp[1] = __floats2half2_rn(o[2], o[3]);
        hp[2] = __floats2half2_rn(o[4], o[5]);
        hp[3] = __floats2half2_rn(o[6], o[7]);
        *(uint4*)&g_H[((size_t)n * RR + r) * DD + c0] = hv;
    }
}

// ===========================================================================
// Fused gather + finalize: one warp per dst node; edge loop unrolled x2.
__global__ __launch_bounds__(256) void k_gather_fin(
    const float* __restrict__ xin, const float* __restrict__ bias,
    const float* __restrict__ gln, const float* __restrict__ bln,
    float* __restrict__ out, int M, int emit_split) {
    int wid = threadIdx.x >> 5, lane = threadIdx.x & 31;
    int n = blockIdx.x * 8 + wid;
    if (n >= M) return;
    int start = g_rowptr[n];
    int deg = g_deg[n];
    int end = start + deg;

    float acc[8];
    {
        const uint4* hs = (const uint4*)&g_H[((size_t)n * RR + (RR - 1)) * DD];
        uint4 v = hs[lane];
        const __half2* hp = (const __half2*)&v;
#pragma unroll
        for (int j = 0; j < 4; j++) {
            float2 p = __half22float2(hp[j]);
            acc[2 * j] = p.x; acc[2 * j + 1] = p.y;
        }
    }
    int i = start;
    for (; i + 1 < end; i += 2) {
        uint32_t pk0 = g_epack[i], pk1 = g_epack[i + 1];
        float w0 = g_ew[i], w1 = g_ew[i + 1];
        const uint4* h0 = (const uint4*)&g_H[((size_t)(pk0 & 0xFFFF) * RR + (pk0 >> 16)) * DD];
        const uint4* h1 = (const uint4*)&g_H[((size_t)(pk1 & 0xFFFF) * RR + (pk1 >> 16)) * DD];
        uint4 u0 = h0[lane];
        uint4 u1 = h1[lane];
        const __half2* p0 = (const __half2*)&u0;
        const __half2* p1 = (const __half2*)&u1;
#pragma unroll
        for (int j = 0; j < 4; j++) {
            float2 a0 = __half22float2(p0[j]);
            float2 a1 = __half22float2(p1[j]);
            acc[2 * j]     += w0 * a0.x + w1 * a1.x;
            acc[2 * j + 1] += w0 * a0.y + w1 * a1.y;
        }
    }
    if (i < end) {
        uint32_t pk = g_epack[i];
        float w = g_ew[i];
        const uint4* h = (const uint4*)&g_H[((size_t)(pk & 0xFFFF) * RR + (pk >> 16)) * DD];
        uint4 u = h[lane];
        const __half2* up = (const __half2*)&u;
#pragma unroll
        for (int j = 0; j < 4; j++) {
            float2 p = __half22float2(up[j]);
            acc[2 * j]     += w * p.x;
            acc[2 * j + 1] += w * p.y;
        }
    }
    float inv = 1.0f / (float)(deg + 1);
    size_t no = (size_t)n * DD + lane * 8;
    int c0 = lane * 8;

    uint4 yv = *(const uint4*)&g_Y[(size_t)n * NCOL + BB * DD + c0];
    const __half2* yp = (const __half2*)&yv;
    float4 xv0 = *(const float4*)&xin[no];
    float4 xv1 = *(const float4*)&xin[no + 4];
    float4 bv0 = *(const float4*)&bias[c0];
    float4 bv1 = *(const float4*)&bias[c0 + 4];

    float val[8];
    {
        float2 y0 = __half22float2(yp[0]), y1 = __half22float2(yp[1]);
        float2 y2 = __half22float2(yp[2]), y3 = __half22float2(yp[3]);
        val[0] = acc[0] * inv + y0.x + bv0.x + xv0.x;
        val[1] = acc[1] * inv + y0.y + bv0.y + xv0.y;
        val[2] = acc[2] * inv + y1.x + bv0.z + xv0.z;
        val[3] = acc[3] * inv + y1.y + bv0.w + xv0.w;
        val[4] = acc[4] * inv + y2.x + bv1.x + xv1.x;
        val[5] = acc[5] * inv + y2.y + bv1.y + xv1.y;
        val[6] = acc[6] * inv + y3.x + bv1.z + xv1.z;
        val[7] = acc[7] * inv + y3.y + bv1.w + xv1.w;
    }
    float s = 0.f;
#pragma unroll
    for (int j = 0; j < 8; j++) s += val[j];
#pragma unroll
    for (int k = 16; k > 0; k >>= 1) s += __shfl_xor_sync(0xffffffffu, s, k);
    float mu = s * (1.0f / DD);
    float s2 = 0.f;
#pragma unroll
    for (int j = 0; j < 8; j++) { float d = val[j] - mu; s2 += d * d; }
#pragma unroll
    for (int k = 16; k > 0; k >>= 1) s2 += __shfl_xor_sync(0xffffffffu, s2, k);
    float rstd = rsqrtf(s2 * (1.0f / DD) + LN_EPS);

    float4 gv0 = *(const float4*)&gln[c0];
    float4 gv1 = *(const float4*)&gln[c0 + 4];
    float4 lb0 = *(const float4*)&bln[c0];
    float4 lb1 = *(const float4*)&bln[c0 + 4];
    float y[8];
    y[0] = fmaxf((val[0] - mu) * rstd * gv0.x + lb0.x, 0.f);
    y[1] = fmaxf((val[1] - mu) * rstd * gv0.y + lb0.y, 0.f);
    y[2] = fmaxf((val[2] - mu) * rstd * gv0.z + lb0.z, 0.f);
    y[3] = fmaxf((val[3] - mu) * rstd * gv0.w + lb0.w, 0.f);
    y[4] = fmaxf((val[4] - mu) * rstd * gv1.x + lb1.x, 0.f);
    y[5] = fmaxf((val[5] - mu) * rstd * gv1.y + lb1.y, 0.f);
    y[6] = fmaxf((val[6] - mu) * rstd * gv1.z + lb1.z, 0.f);
    y[7] = fmaxf((val[7] - mu) * rstd * gv1.w + lb1.w, 0.f);

    *(float4*)&out[no]     = make_float4(y[0], y[1], y[2], y[3]);
    *(float4*)&out[no + 4] = make_float4(y[4], y[5], y[6], y[7]);
    if (emit_split) {
        uint4 hv;
        __half2* hp = (__half2*)&hv;
        hp[0] = __floats2half2_rn(y[0], y[1]);
        hp[1] = __floats2half2_rn(y[2], y[3]);
        hp[2] = __floats2half2_rn(y[4], y[5]);
        hp[3] = __floats2half2_rn(y[6], y[7]);
        *(uint4*)&g_Ap[(size_t)n * KK + c0] = hv;
    }
}

// ===========================================================================
static void run_layer(const float* x, const float* basis, const float* att,
                      const float* root, const float* bias,
                      const float* lg, const float* lb,
                      float* out, int M, int emit_split) {
    k_prepw<<<NCOL, 256>>>(basis, root);
    {
        dim3 grid(NCOL / 128, (M + 127) / 128);   // (18, 391)
        k_gemm_mma<<<grid, 256, 4 * TILE_B>>>(M);
    }
    k_expand<<<(M + 7) / 8, 256>>>(att, M);
    k_gather_fin<<<(M + 7) / 8, 256>>>(x, bias, lg, lb, out, M, emit_split);
}

extern "C" void kernel_launch(void* const* d_in, const int* in_sizes, int n_in,
                              void* d_out, int out_size) {
    const float* x   = (const float*)d_in[0];
    const int*   ei  = (const int*)d_in[1];
    const int*   et  = (const int*)d_in[2];
    const float* ea  = (const float*)d_in[3];
    const float* basis1 = (const float*)d_in[4];
    const float* att1   = (const float*)d_in[5];
    const float* root1  = (const float*)d_in[6];
    const float* bias1  = (const float*)d_in[7];
    const float* ln1g   = (const float*)d_in[8];
    const float* ln1b   = (const float*)d_in[9];
    const float* basis2 = (const float*)d_in[10];
    const float* att2   = (const float*)d_in[11];
    const float* root2  = (const float*)d_in[12];
    const float* bias2  = (const float*)d_in[13];
    const float* ln2g   = (const float*)d_in[14];
    const float* ln2b   = (const float*)d_in[15];
    float* out = (float*)d_out;

    int M = in_sizes[0] / DD;     // 50000
    int E = in_sizes[2];          // 800000

    cudaFuncSetAttribute(k_gemm_mma, cudaFuncAttributeMaxDynamicSharedMemorySize,
                         4 * TILE_B);

    void* p = nullptr;
    cudaGetSymbolAddress(&p, g_x1);
    float* x1_dev = (float*)p;

    // CSR over dst (shared by both layers)
    int nb = (M + 255) / 256;                  // 196
    k_zero_degfill<<<nb, 256>>>(M);
    k_deg_count<<<(E + 255) / 256, 256>>>(ei, E);
    k_scan1<<<nb, 256>>>(M);
    k_scan2<<<1, 256>>>(nb);
    k_scan3<<<nb, 256>>>(M);
    k_fill<<<(E + 255) / 256, 256>>>(ei, et, ea, E);

    // layer 1
    k_cvt_x<<<(M * DD + 255) / 256, 256>>>(x, M);
    run_layer(x, basis1, att1, root1, bias1, ln1g, ln1b, x1_dev, M, 1);
    // layer 2 (g_Ap emitted by layer-1 gather_fin)
    run_layer(x1_dev, basis2, att2, root2, bias2, ln2g, ln2b, out, M, 0);
}